// round 1
// baseline (speedup 1.0000x reference)
#include <cuda_runtime.h>
#include <cuda_bf16.h>

// Problem constants
#define Nn 8
#define Cc 64
#define Hh 96
#define Ww 96
#define COo 64
#define KK9 9
#define HW 9216           // 96*96
#define NPIX 73728        // 8*9216

// ---------------- scratch (device globals; no allocation allowed) ----------------
__device__ float g_xt[Nn * Hh * Ww * Cc];     // x transposed to NHWC
__device__ float g_offm[NPIX * 32];           // per-pixel: ch0..17 offsets, 18..26 sigmoid(mask)
__device__ float g_wt[KK9 * Cc * COo];        // weight transposed to [k][c][co]

// ---------------- kernel 0: x NCHW -> NHWC (tiled transpose) ----------------
__global__ void k_transpose_x(const float* __restrict__ x) {
    __shared__ float tile[32][33];
    int z = blockIdx.z;            // n*96 + y
    int n = z / Hh;
    int y = z % Hh;
    int xb = blockIdx.x * 32;      // W tile (3 tiles)
    int cb = blockIdx.y * 32;      // C tile (2 tiles)
    int tx = threadIdx.x, ty = threadIdx.y;
#pragma unroll
    for (int k = 0; k < 4; k++) {
        int c = cb + ty + k * 8;
        tile[ty + k * 8][tx] = x[((n * Cc + c) * Hh + y) * Ww + xb + tx];
    }
    __syncthreads();
#pragma unroll
    for (int k = 0; k < 4; k++) {
        int xo = xb + ty + k * 8;
        g_xt[((n * Hh + y) * Ww + xo) * Cc + cb + tx] = tile[tx][ty + k * 8];
    }
}

// ---------------- kernel 0b: weight [co][c][3][3] -> g_wt[k][c][co] ----------------
__global__ void k_transpose_w(const float* __restrict__ weight) {
    int i = blockIdx.x * blockDim.x + threadIdx.x;   // i = k*4096 + c*64 + co
    if (i < KK9 * Cc * COo) {
        int co = i & 63;
        int c = (i >> 6) & 63;
        int k = i >> 12;
        g_wt[i] = weight[(co * Cc + c) * KK9 + k];
    }
}

// ---------------- kernel 1: offset conv (64->27, 3x3, pad 1) + sigmoid on mask ----------------
__global__ void k_offconv(const float* __restrict__ x,
                          const float* __restrict__ w_off,
                          const float* __restrict__ b_off) {
    __shared__ float ws[Cc * 28];   // per-tap weights, ch padded 27->28 for float4
    int tid = threadIdx.x;
    int p = blockIdx.x * 128 + tid;           // NPIX = 576*128 exactly
    int n = p / HW;
    int rem = p % HW;
    int y = rem / Ww;
    int xq = rem % Ww;

    float acc[28];
#pragma unroll
    for (int ch = 0; ch < 27; ch++) acc[ch] = b_off[ch];
    acc[27] = 0.f;

    for (int ky = 0; ky < 3; ky++) {
        for (int kx = 0; kx < 3; kx++) {
            int kidx = ky * 3 + kx;
            __syncthreads();
            for (int i = tid; i < Cc * 28; i += 128) {
                int c = i / 28;
                int ch = i % 28;
                ws[i] = (ch < 27) ? w_off[ch * (Cc * KK9) + c * KK9 + kidx] : 0.f;
            }
            __syncthreads();
            int yy = y + ky - 1, xx = xq + kx - 1;
            if (yy >= 0 && yy < Hh && xx >= 0 && xx < Ww) {
                const float* xp = x + (size_t)n * Cc * HW + yy * Ww + xx;
#pragma unroll 4
                for (int c = 0; c < Cc; c++) {
                    float v = xp[c * HW];
                    const float4* w4 = (const float4*)&ws[c * 28];
#pragma unroll
                    for (int q = 0; q < 7; q++) {
                        float4 w = w4[q];
                        acc[q * 4 + 0] += v * w.x;
                        acc[q * 4 + 1] += v * w.y;
                        acc[q * 4 + 2] += v * w.z;
                        acc[q * 4 + 3] += v * w.w;
                    }
                }
            }
        }
    }
#pragma unroll
    for (int ch = 0; ch < 27; ch++) {
        float v = acc[ch];
        if (ch >= 18) v = 1.f / (1.f + __expf(-v));   // sigmoid mask
        g_offm[p * 32 + ch] = v;
    }
}

// ---------------- kernel 2: fused bilinear-gather + GEMM ----------------
// out[co][pix] = sum_{t,c} wt[t][c][co] * val[t][c][pix] + bias[co]
// Block tile: 64 co x 64 pixels; 128 threads; each thread: 8co x 4pix accumulators.
__global__ void k_deform(const float* __restrict__ bias, float* __restrict__ out) {
    __shared__ float4 entW[576];      // 4 bilinear weights (mask+validity folded) per (tap,pixLocal)
    __shared__ int    entB[576];      // NHWC base offset of corner (y0,x0) clamped
    __shared__ int    entD[576];      // packed: ddx | (ddy<<16)
    __shared__ float  valS[64 * 68];  // [c][pix], stride 68 (pad to dodge bank conflicts, 16B-aligned rows)
    __shared__ float  wtS[64 * 64];   // [c][co]

    int tid = threadIdx.x;
    int pix0 = blockIdx.x * 64;
    int nb = pix0 / HW;               // whole tile is inside one n (9216 % 64 == 0)
    int rem0 = pix0 % HW;

    // -------- setup: per (tap, pixel) bilinear metadata --------
    for (int e = tid; e < 576; e += 128) {
        int t = e >> 6;
        int pl = e & 63;
        int p = pix0 + pl;
        int rem = rem0 + pl;
        int y = rem / Ww;
        int x = rem % Ww;
        float dy = g_offm[p * 32 + 2 * t];
        float dx = g_offm[p * 32 + 2 * t + 1];
        float m = g_offm[p * 32 + 18 + t];
        int ky = t / 3, kx = t % 3;
        float py = (float)(y + ky - 1) + dy;
        float px = (float)(x + kx - 1) + dx;
        float fy = floorf(py), fx = floorf(px);
        float ly = py - fy, lx = px - fx;
        int iy = (int)fy, ix = (int)fx;
        float hy0 = (iy >= 0 && iy < Hh) ? (1.f - ly) : 0.f;
        float hy1 = (iy >= -1 && iy < Hh - 1) ? ly : 0.f;
        float hx0 = (ix >= 0 && ix < Ww) ? (1.f - lx) : 0.f;
        float hx1 = (ix >= -1 && ix < Ww - 1) ? lx : 0.f;
        int iyc = min(max(iy, 0), Hh - 1);
        int ixc = min(max(ix, 0), Ww - 1);
        int ddy = (iy >= 0 && iy < Hh - 1) ? Ww * Cc : 0;
        int ddx = (ix >= 0 && ix < Ww - 1) ? Cc : 0;
        entB[e] = ((nb * Hh + iyc) * Ww + ixc) * Cc;
        entD[e] = ddx | (ddy << 16);
        entW[e] = make_float4(hy0 * hx0 * m, hy0 * hx1 * m, hy1 * hx0 * m, hy1 * hx1 * m);
    }
    __syncthreads();

    float acc[8][4];
#pragma unroll
    for (int i = 0; i < 8; i++)
#pragma unroll
        for (int j = 0; j < 4; j++) acc[i][j] = 0.f;

    int tx = tid & 15;   // pixel group: pix = tx*4 + j
    int ty = tid >> 4;   // co group:    co  = ty*8 + i

    for (int t = 0; t < KK9; t++) {
        // stage weight slice [c][co] for this tap
        {
            const float4* gw = (const float4*)&g_wt[t * 4096];
            float4* ws4 = (float4*)wtS;
            for (int i = tid; i < 1024; i += 128) ws4[i] = gw[i];
        }
        // compute val slice [c][pix] via bilinear gather (coalesced over c)
        {
            int c = tid & 63;
            int half = tid >> 6;
#pragma unroll 4
            for (int s = 0; s < 32; s++) {
                int pl = s * 2 + half;
                int e = t * 64 + pl;
                float4 w = entW[e];
                int base = entB[e] + c;
                int dd = entD[e];
                int ddx = dd & 0xffff;
                int ddy = dd >> 16;
                float v = w.x * g_xt[base]
                        + w.y * g_xt[base + ddx]
                        + w.z * g_xt[base + ddy]
                        + w.w * g_xt[base + ddy + ddx];
                valS[c * 68 + pl] = v;
            }
        }
        __syncthreads();

        // register-tiled GEMM over this tap's 64 channels
#pragma unroll 4
        for (int c = 0; c < 64; c++) {
            float4 bv = *(const float4*)&valS[c * 68 + tx * 4];
            float4 a0 = *(const float4*)&wtS[c * 64 + ty * 8];
            float4 a1 = *(const float4*)&wtS[c * 64 + ty * 8 + 4];
            float a[8] = {a0.x, a0.y, a0.z, a0.w, a1.x, a1.y, a1.z, a1.w};
            float b[4] = {bv.x, bv.y, bv.z, bv.w};
#pragma unroll
            for (int i = 0; i < 8; i++)
#pragma unroll
                for (int j = 0; j < 4; j++) acc[i][j] += a[i] * b[j];
        }
        __syncthreads();   // protect smem before next tap overwrites
    }

    // -------- epilogue: coalesced float4 stores into NCHW output --------
#pragma unroll
    for (int i = 0; i < 8; i++) {
        int co = ty * 8 + i;
        float bv = bias[co];
        float4 o;
        o.x = acc[i][0] + bv;
        o.y = acc[i][1] + bv;
        o.z = acc[i][2] + bv;
        o.w = acc[i][3] + bv;
        *(float4*)&out[((size_t)nb * COo + co) * HW + rem0 + tx * 4] = o;
    }
}

// ---------------- launch ----------------
extern "C" void kernel_launch(void* const* d_in, const int* in_sizes, int n_in,
                              void* d_out, int out_size) {
    const float* x      = (const float*)d_in[0];
    const float* w_off  = (const float*)d_in[1];
    const float* b_off  = (const float*)d_in[2];
    const float* weight = (const float*)d_in[3];
    const float* bias   = (const float*)d_in[4];
    float* out = (float*)d_out;

    k_transpose_x<<<dim3(3, 2, Nn * Hh), dim3(32, 8)>>>(x);
    k_transpose_w<<<144, 256>>>(weight);
    k_offconv<<<NPIX / 128, 128>>>(x, w_off, b_off);
    k_deform<<<NPIX / 64, 128>>>(bias, out);
}

// round 2
// speedup vs baseline: 1.1723x; 1.1723x over previous
#include <cuda_runtime.h>
#include <cuda_bf16.h>

// Problem constants
#define Nn 8
#define Cc 64
#define Hh 96
#define Ww 96
#define COo 64
#define KK9 9
#define HW 9216           // 96*96
#define NPIX 73728        // 8*9216

// ---------------- scratch (device globals; no allocation allowed) ----------------
__device__ float g_xt[Nn * Hh * Ww * Cc];     // x transposed to NHWC
__device__ float g_offm[NPIX * 32];           // per-pixel: ch0..17 offsets, 18..26 sigmoid(mask)
__device__ float g_wt[KK9 * Cc * COo];        // weight transposed to [k][c][co]

// ---------------- kernel 0: x NCHW -> NHWC (tiled transpose) ----------------
__global__ void k_transpose_x(const float* __restrict__ x) {
    __shared__ float tile[32][33];
    int z = blockIdx.z;            // n*96 + y
    int n = z / Hh;
    int y = z % Hh;
    int xb = blockIdx.x * 32;      // W tile (3 tiles)
    int cb = blockIdx.y * 32;      // C tile (2 tiles)
    int tx = threadIdx.x, ty = threadIdx.y;
#pragma unroll
    for (int k = 0; k < 4; k++) {
        int c = cb + ty + k * 8;
        tile[ty + k * 8][tx] = x[((n * Cc + c) * Hh + y) * Ww + xb + tx];
    }
    __syncthreads();
#pragma unroll
    for (int k = 0; k < 4; k++) {
        int xo = xb + ty + k * 8;
        g_xt[((n * Hh + y) * Ww + xo) * Cc + cb + tx] = tile[tx][ty + k * 8];
    }
}

// ---------------- kernel 0b: weight [co][c][3][3] -> g_wt[k][c][co] ----------------
__global__ void k_transpose_w(const float* __restrict__ weight) {
    int i = blockIdx.x * blockDim.x + threadIdx.x;   // i = k*4096 + c*64 + co
    if (i < KK9 * Cc * COo) {
        int co = i & 63;
        int c = (i >> 6) & 63;
        int k = i >> 12;
        g_wt[i] = weight[(co * Cc + c) * KK9 + k];
    }
}

// ---------------- kernel 1: offset conv (64->27, 3x3, pad 1) + sigmoid on mask ----------------
__global__ void k_offconv(const float* __restrict__ x,
                          const float* __restrict__ w_off,
                          const float* __restrict__ b_off) {
    __shared__ float ws[Cc * 28];   // per-tap weights, ch padded 27->28 for float4
    int tid = threadIdx.x;
    int p = blockIdx.x * 128 + tid;           // NPIX = 576*128 exactly
    int n = p / HW;
    int rem = p % HW;
    int y = rem / Ww;
    int xq = rem % Ww;

    float acc[28];
#pragma unroll
    for (int ch = 0; ch < 27; ch++) acc[ch] = b_off[ch];
    acc[27] = 0.f;

    for (int ky = 0; ky < 3; ky++) {
        for (int kx = 0; kx < 3; kx++) {
            int kidx = ky * 3 + kx;
            __syncthreads();
            for (int i = tid; i < Cc * 28; i += 128) {
                int c = i / 28;
                int ch = i % 28;
                ws[i] = (ch < 27) ? w_off[ch * (Cc * KK9) + c * KK9 + kidx] : 0.f;
            }
            __syncthreads();
            int yy = y + ky - 1, xx = xq + kx - 1;
            if (yy >= 0 && yy < Hh && xx >= 0 && xx < Ww) {
                const float* xp = x + (size_t)n * Cc * HW + yy * Ww + xx;
#pragma unroll 4
                for (int c = 0; c < Cc; c++) {
                    float v = xp[c * HW];
                    const float4* w4 = (const float4*)&ws[c * 28];
#pragma unroll
                    for (int q = 0; q < 7; q++) {
                        float4 w = w4[q];
                        acc[q * 4 + 0] += v * w.x;
                        acc[q * 4 + 1] += v * w.y;
                        acc[q * 4 + 2] += v * w.z;
                        acc[q * 4 + 3] += v * w.w;
                    }
                }
            }
        }
    }
#pragma unroll
    for (int ch = 0; ch < 27; ch++) {
        float v = acc[ch];
        if (ch >= 18) v = 1.f / (1.f + __expf(-v));   // sigmoid mask
        g_offm[p * 32 + ch] = v;
    }
}

// ---------------- kernel 2: fused bilinear-gather + GEMM (v2) ----------------
// out[co][pix] = sum_{t,c} wt[t][c][co] * val[t][c][pix] + bias[co]
// Block tile: 64 co x 128 pixels; 256 threads; each thread: 8co x 4pix accumulators.
// Per-tap bilinear metadata (small smem) -> 53.2 KB total -> 4 CTAs/SM (32 warps).
#define VAL_STRIDE 132

__global__ void __launch_bounds__(256, 4) k_deform(const float* __restrict__ bias,
                                                   float* __restrict__ out) {
    extern __shared__ char smem_raw[];
    float*  valS = (float*)smem_raw;                    // [64][132]  33792 B
    float*  wtS  = valS + 64 * VAL_STRIDE;              // [64][64]   16384 B
    float4* entW = (float4*)(wtS + 64 * 64);            // [128]       2048 B
    int*    entB = (int*)(entW + 128);                  // [128]        512 B
    int*    entD = entB + 128;                          // [128]        512 B

    int tid = threadIdx.x;
    int pix0 = blockIdx.x * 128;
    int nb = pix0 / HW;               // whole tile inside one n (9216 % 128 == 0)
    int rem0 = pix0 % HW;

    float acc[8][4];
#pragma unroll
    for (int i = 0; i < 8; i++)
#pragma unroll
        for (int j = 0; j < 4; j++) acc[i][j] = 0.f;

    int tx = tid & 31;   // pixel group: pix = tx*4 + j
    int ty = tid >> 5;   // co group:    co  = ty*8 + i

    for (int t = 0; t < KK9; t++) {
        // stage weight slice [c][co] for this tap
        {
            const float4* gw = (const float4*)&g_wt[t * 4096];
            float4* ws4 = (float4*)wtS;
#pragma unroll
            for (int k = 0; k < 4; k++) ws4[tid + k * 256] = gw[tid + k * 256];
        }
        // compute per-pixel bilinear metadata for this tap
        if (tid < 128) {
            int pl = tid;
            int p = pix0 + pl;
            int rem = rem0 + pl;
            int y = rem / Ww;
            int x = rem % Ww;
            float dy = g_offm[p * 32 + 2 * t];
            float dx = g_offm[p * 32 + 2 * t + 1];
            float m = g_offm[p * 32 + 18 + t];
            int ky = t / 3, kx = t % 3;
            float py = (float)(y + ky - 1) + dy;
            float px = (float)(x + kx - 1) + dx;
            float fy = floorf(py), fx = floorf(px);
            float ly = py - fy, lx = px - fx;
            int iy = (int)fy, ix = (int)fx;
            float hy0 = (iy >= 0 && iy < Hh) ? (1.f - ly) : 0.f;
            float hy1 = (iy >= -1 && iy < Hh - 1) ? ly : 0.f;
            float hx0 = (ix >= 0 && ix < Ww) ? (1.f - lx) : 0.f;
            float hx1 = (ix >= -1 && ix < Ww - 1) ? lx : 0.f;
            int iyc = min(max(iy, 0), Hh - 1);
            int ixc = min(max(ix, 0), Ww - 1);
            int ddy = (iy >= 0 && iy < Hh - 1) ? Ww * Cc : 0;
            int ddx = (ix >= 0 && ix < Ww - 1) ? Cc : 0;
            entB[pl] = ((nb * Hh + iyc) * Ww + ixc) * Cc;
            entD[pl] = ddx | (ddy << 16);
            entW[pl] = make_float4(hy0 * hx0 * m, hy0 * hx1 * m, hy1 * hx0 * m, hy1 * hx1 * m);
        }
        __syncthreads();

        // bilinear gather into valS[c][pix] (coalesced 256B over c per corner)
        {
            int c = tid & 63;
            int q = tid >> 6;           // 0..3
#pragma unroll 4
            for (int s = 0; s < 32; s++) {
                int pl = s * 4 + q;
                float4 w = entW[pl];
                int base = entB[pl] + c;
                int dd = entD[pl];
                int ddx = dd & 0xffff;
                int ddy = dd >> 16;
                float v = w.x * g_xt[base]
                        + w.y * g_xt[base + ddx]
                        + w.z * g_xt[base + ddy]
                        + w.w * g_xt[base + ddy + ddx];
                valS[c * VAL_STRIDE + pl] = v;
            }
        }
        __syncthreads();

        // register-tiled GEMM over this tap's 64 channels
#pragma unroll 4
        for (int c = 0; c < 64; c++) {
            float4 bv = *(const float4*)&valS[c * VAL_STRIDE + tx * 4];
            float4 a0 = *(const float4*)&wtS[c * 64 + ty * 8];
            float4 a1 = *(const float4*)&wtS[c * 64 + ty * 8 + 4];
            float a[8] = {a0.x, a0.y, a0.z, a0.w, a1.x, a1.y, a1.z, a1.w};
            float b[4] = {bv.x, bv.y, bv.z, bv.w};
#pragma unroll
            for (int i = 0; i < 8; i++)
#pragma unroll
                for (int j = 0; j < 4; j++) acc[i][j] += a[i] * b[j];
        }
        __syncthreads();   // protect smem before next tap overwrites
    }

    // -------- epilogue: coalesced float4 stores into NCHW output --------
#pragma unroll
    for (int i = 0; i < 8; i++) {
        int co = ty * 8 + i;
        float bv = bias[co];
        float4 o;
        o.x = acc[i][0] + bv;
        o.y = acc[i][1] + bv;
        o.z = acc[i][2] + bv;
        o.w = acc[i][3] + bv;
        *(float4*)&out[((size_t)nb * COo + co) * HW + rem0 + tx * 4] = o;
    }
}

#define DEFORM_SMEM (64 * VAL_STRIDE * 4 + 64 * 64 * 4 + 128 * 16 + 128 * 4 + 128 * 4)

// ---------------- launch ----------------
extern "C" void kernel_launch(void* const* d_in, const int* in_sizes, int n_in,
                              void* d_out, int out_size) {
    const float* x      = (const float*)d_in[0];
    const float* w_off  = (const float*)d_in[1];
    const float* b_off  = (const float*)d_in[2];
    const float* weight = (const float*)d_in[3];
    const float* bias   = (const float*)d_in[4];
    float* out = (float*)d_out;

    static int attr_set = 0;
    if (!attr_set) {
        cudaFuncSetAttribute(k_deform, cudaFuncAttributeMaxDynamicSharedMemorySize, DEFORM_SMEM);
        attr_set = 1;
    }

    k_transpose_x<<<dim3(3, 2, Nn * Hh), dim3(32, 8)>>>(x);
    k_transpose_w<<<144, 256>>>(weight);
    k_offconv<<<NPIX / 128, 128>>>(x, w_off, b_off);
    k_deform<<<NPIX / 128, 256, DEFORM_SMEM>>>(bias, out);
}

// round 5
// speedup vs baseline: 1.2262x; 1.0459x over previous
#include <cuda_runtime.h>
#include <cuda_bf16.h>
#include <cstdint>

// Problem constants
#define Nn 8
#define Cc 64
#define Hh 96
#define Ww 96
#define COo 64
#define KK9 9
#define HW 9216           // 96*96
#define NPIX 73728        // 8*9216

// ---------------- scratch (device globals; no allocation allowed) ----------------
__device__ float g_xt[Nn * Hh * Ww * Cc];              // x transposed to NHWC
__device__ float g_offm[NPIX * 32];                    // per-pixel offsets + sigmoid(mask)
__device__ __align__(16) uint32_t g_wt[KK9 * 4096];    // per-tap [co][c] tf32 bits

static __device__ __forceinline__ uint32_t f2tf32(float v) {
    uint32_t r;
    asm("cvt.rna.tf32.f32 %0, %1;" : "=r"(r) : "f"(v));
    return r;
}

static __device__ __forceinline__ void mma_tf32(float* d, const uint32_t* a, const uint32_t* b) {
    asm volatile("mma.sync.aligned.m16n8k8.row.col.f32.tf32.tf32.f32 "
                 "{%0,%1,%2,%3}, {%4,%5,%6,%7}, {%8,%9}, {%0,%1,%2,%3};"
                 : "+f"(d[0]), "+f"(d[1]), "+f"(d[2]), "+f"(d[3])
                 : "r"(a[0]), "r"(a[1]), "r"(a[2]), "r"(a[3]), "r"(b[0]), "r"(b[1]));
}

// ---------------- kernel 0: x NCHW -> NHWC (tiled transpose) ----------------
__global__ void k_transpose_x(const float* __restrict__ x) {
    __shared__ float tile[32][33];
    int z = blockIdx.z;
    int n = z / Hh;
    int y = z % Hh;
    int xb = blockIdx.x * 32;
    int cb = blockIdx.y * 32;
    int tx = threadIdx.x, ty = threadIdx.y;
#pragma unroll
    for (int k = 0; k < 4; k++) {
        int c = cb + ty + k * 8;
        tile[ty + k * 8][tx] = x[((n * Cc + c) * Hh + y) * Ww + xb + tx];
    }
    __syncthreads();
#pragma unroll
    for (int k = 0; k < 4; k++) {
        int xo = xb + ty + k * 8;
        g_xt[((n * Hh + y) * Ww + xo) * Cc + cb + tx] = tile[tx][ty + k * 8];
    }
}

// ---------------- kernel 0b: weight [co][c][3][3] -> g_wt[t][co][c] (tf32) ----------------
__global__ void k_transpose_w(const float* __restrict__ weight) {
    int i = blockIdx.x * 256 + threadIdx.x;   // t*4096 + co*64 + c
    if (i < KK9 * 4096) {
        int c = i & 63;
        int co = (i >> 6) & 63;
        int t = i >> 12;
        g_wt[i] = f2tf32(weight[(co * Cc + c) * KK9 + t]);
    }
}

// ---------------- kernel 1: offset conv (64->27, 3x3, pad 1) + sigmoid on mask ----------------
__global__ void k_offconv(const float* __restrict__ x,
                          const float* __restrict__ w_off,
                          const float* __restrict__ b_off) {
    __shared__ float ws[Cc * 28];
    int tid = threadIdx.x;
    int p = blockIdx.x * 128 + tid;
    int n = p / HW;
    int rem = p % HW;
    int y = rem / Ww;
    int xq = rem % Ww;

    float acc[28];
#pragma unroll
    for (int ch = 0; ch < 27; ch++) acc[ch] = b_off[ch];
    acc[27] = 0.f;

    for (int ky = 0; ky < 3; ky++) {
        for (int kx = 0; kx < 3; kx++) {
            int kidx = ky * 3 + kx;
            __syncthreads();
            for (int i = tid; i < Cc * 28; i += 128) {
                int c = i / 28;
                int ch = i % 28;
                ws[i] = (ch < 27) ? w_off[ch * (Cc * KK9) + c * KK9 + kidx] : 0.f;
            }
            __syncthreads();
            int yy = y + ky - 1, xx = xq + kx - 1;
            if (yy >= 0 && yy < Hh && xx >= 0 && xx < Ww) {
                const float* xp = x + (size_t)n * Cc * HW + yy * Ww + xx;
#pragma unroll 4
                for (int c = 0; c < Cc; c++) {
                    float v = xp[c * HW];
                    const float4* w4 = (const float4*)&ws[c * 28];
#pragma unroll
                    for (int q = 0; q < 7; q++) {
                        float4 w = w4[q];
                        acc[q * 4 + 0] += v * w.x;
                        acc[q * 4 + 1] += v * w.y;
                        acc[q * 4 + 2] += v * w.z;
                        acc[q * 4 + 3] += v * w.w;
                    }
                }
            }
        }
    }
#pragma unroll
    for (int ch = 0; ch < 27; ch++) {
        float v = acc[ch];
        if (ch >= 18) v = 1.f / (1.f + __expf(-v));
        g_offm[p * 32 + ch] = v;
    }
}

// ---------------- kernel 2: fused bilinear-gather + mma.sync tf32 GEMM ----------------
// out[co][pix] = sum_{t,c} wt[co][c] * val[pix][c] + bias[co]
// Block: 128pix x 64co; 256 threads (8 warps); warp tile 32pix x 32co via
// m16n8k8 tf32 mma (2x4 grid, 8 k-steps per tap).
// SMEM: valS [128pix][68] tf32 | wtS [64co][68] tf32 | entW/entB/entD metadata
#define A_STRIDE 68
#define O_STRIDE 132
#define SM_VAL  0
#define SM_WT   (128 * A_STRIDE * 4)                 // 34816
#define SM_ENTW (SM_WT + 64 * A_STRIDE * 4)          // 52224
#define SM_ENTB (SM_ENTW + 2048)                     // 54272
#define SM_ENTD (SM_ENTB + 512)                      // 54784
#define DEFORM_SMEM (SM_ENTD + 512)                  // 55296

__global__ void __launch_bounds__(256, 3) k_deform(const float* __restrict__ bias,
                                                   float* __restrict__ out) {
    extern __shared__ char base[];
    uint32_t* valS = (uint32_t*)(base + SM_VAL);
    uint32_t* wtS  = (uint32_t*)(base + SM_WT);
    float4*   entW = (float4*)(base + SM_ENTW);
    int*      entB = (int*)(base + SM_ENTB);
    int*      entD = (int*)(base + SM_ENTD);
    float*    outS = (float*)base;                   // epilogue overlay [64co][132]

    int tid = threadIdx.x;
    int wid = tid >> 5;
    int lane = tid & 31;
    int pix0 = blockIdx.x * 128;
    int nb = pix0 / HW;
    int rem0 = pix0 % HW;

    int wm = (wid & 3) * 32;      // warp pixel base
    int wn = (wid >> 2) * 32;     // warp co base
    int lg = lane >> 2;           // group id (0..7)
    int lt = lane & 3;            // thread-in-group (0..3)

    float acc[2][4][4];
#pragma unroll
    for (int mt = 0; mt < 2; mt++)
#pragma unroll
        for (int nt = 0; nt < 4; nt++)
#pragma unroll
            for (int r = 0; r < 4; r++) acc[mt][nt][r] = 0.f;

    int cg = tid & 63;            // gather channel lane
    int q = tid >> 6;             // gather pixel phase

    for (int t = 0; t < KK9; t++) {
        // ---- stage weights [co][c] -> wtS stride 68 ----
        {
            const uint4* gw = (const uint4*)(g_wt + t * 4096);
#pragma unroll
            for (int i = 0; i < 4; i++) {
                int e = tid + i * 256;
                uint4 v = gw[e];
                int co = e >> 4;
                int c4 = (e & 15) << 2;
                uint32_t* d = &wtS[co * A_STRIDE + c4];
                d[0] = v.x; d[1] = v.y; d[2] = v.z; d[3] = v.w;
            }
        }
        // ---- per-pixel bilinear metadata for this tap ----
        if (tid < 128) {
            int pl = tid;
            int p = pix0 + pl;
            int rem = rem0 + pl;
            int y = rem / Ww;
            int x = rem % Ww;
            float dy = g_offm[p * 32 + 2 * t];
            float dx = g_offm[p * 32 + 2 * t + 1];
            float m = g_offm[p * 32 + 18 + t];
            int ky = t / 3, kx = t % 3;
            float py = (float)(y + ky - 1) + dy;
            float px = (float)(x + kx - 1) + dx;
            float fy = floorf(py), fx = floorf(px);
            float ly = py - fy, lx = px - fx;
            int iy = (int)fy, ix = (int)fx;
            float hy0 = (iy >= 0 && iy < Hh) ? (1.f - ly) : 0.f;
            float hy1 = (iy >= -1 && iy < Hh - 1) ? ly : 0.f;
            float hx0 = (ix >= 0 && ix < Ww) ? (1.f - lx) : 0.f;
            float hx1 = (ix >= -1 && ix < Ww - 1) ? lx : 0.f;
            int iyc = min(max(iy, 0), Hh - 1);
            int ixc = min(max(ix, 0), Ww - 1);
            int ddy = (iy >= 0 && iy < Hh - 1) ? Ww * Cc : 0;
            int ddx = (ix >= 0 && ix < Ww - 1) ? Cc : 0;
            entB[pl] = ((nb * Hh + iyc) * Ww + ixc) * Cc;
            entD[pl] = ddx | (ddy << 16);
            entW[pl] = make_float4(hy0 * hx0 * m, hy0 * hx1 * m, hy1 * hx0 * m, hy1 * hx1 * m);
        }
        __syncthreads();

        // ---- bilinear gather -> valS[pix][c] tf32 (conflict-free STS) ----
#pragma unroll 4
        for (int s = 0; s < 32; s++) {
            int pl = s * 4 + q;
            float4 w = entW[pl];
            int gbase = entB[pl] + cg;
            int dd = entD[pl];
            int ddx = dd & 0xffff;
            int ddy = dd >> 16;
            float v = w.x * g_xt[gbase]
                    + w.y * g_xt[gbase + ddx]
                    + w.z * g_xt[gbase + ddy]
                    + w.w * g_xt[gbase + ddy + ddx];
            valS[pl * A_STRIDE + cg] = f2tf32(v);
        }
        __syncthreads();

        // ---- tensor-core GEMM for this tap (K = 64, 8 k-steps) ----
#pragma unroll
        for (int kk = 0; kk < 8; kk++) {
            int k0 = kk * 8;
            uint32_t a[2][4];
#pragma unroll
            for (int mt = 0; mt < 2; mt++) {
                const uint32_t* ap = &valS[(wm + mt * 16 + lg) * A_STRIDE + k0 + lt];
                a[mt][0] = ap[0];
                a[mt][1] = ap[8 * A_STRIDE];
                a[mt][2] = ap[4];
                a[mt][3] = ap[8 * A_STRIDE + 4];
            }
            uint32_t b[4][2];
#pragma unroll
            for (int nt = 0; nt < 4; nt++) {
                const uint32_t* bp = &wtS[(wn + nt * 8 + lg) * A_STRIDE + k0 + lt];
                b[nt][0] = bp[0];
                b[nt][1] = bp[4];
            }
#pragma unroll
            for (int mt = 0; mt < 2; mt++)
#pragma unroll
                for (int nt = 0; nt < 4; nt++)
                    mma_tf32(acc[mt][nt], a[mt], b[nt]);
        }
        __syncthreads();   // protect valS/wtS before next tap overwrites
    }

    // ---- epilogue: fragments -> smem [co][pix] -> coalesced NCHW stores ----
#pragma unroll
    for (int mt = 0; mt < 2; mt++)
#pragma unroll
        for (int nt = 0; nt < 4; nt++)
#pragma unroll
            for (int r = 0; r < 4; r++) {
                int pix = wm + mt * 16 + ((r >> 1) << 3) + lg;
                int co = wn + nt * 8 + 2 * lt + (r & 1);
                outS[co * O_STRIDE + pix] = acc[mt][nt][r];
            }
    __syncthreads();

#pragma unroll
    for (int i = 0; i < 8; i++) {
        int co = i * 8 + (tid >> 5);
        int px = (tid & 31) * 4;
        float4 v = *(const float4*)&outS[co * O_STRIDE + px];
        float bv = __ldg(&bias[co]);
        v.x += bv; v.y += bv; v.z += bv; v.w += bv;
        *(float4*)&out[((size_t)nb * COo + co) * HW + rem0 + px] = v;
    }
}

// ---------------- launch ----------------
extern "C" void kernel_launch(void* const* d_in, const int* in_sizes, int n_in,
                              void* d_out, int out_size) {
    const float* x      = (const float*)d_in[0];
    const float* w_off  = (const float*)d_in[1];
    const float* b_off  = (const float*)d_in[2];
    const float* weight = (const float*)d_in[3];
    const float* bias   = (const float*)d_in[4];
    float* out = (float*)d_out;

    static int attr_set = 0;
    if (!attr_set) {
        cudaFuncSetAttribute(k_deform, cudaFuncAttributeMaxDynamicSharedMemorySize, DEFORM_SMEM);
        attr_set = 1;
    }

    k_transpose_x<<<dim3(3, 2, Nn * Hh), dim3(32, 8)>>>(x);
    k_transpose_w<<<144, 256>>>(weight);
    k_offconv<<<NPIX / 128, 128>>>(x, w_off, b_off);
    k_deform<<<NPIX / 128, 256, DEFORM_SMEM>>>(bias, out);
}

// round 6
// speedup vs baseline: 2.0178x; 1.6456x over previous
#include <cuda_runtime.h>
#include <cuda_bf16.h>
#include <cstdint>

// Problem constants
#define Nn 8
#define Cc 64
#define Hh 96
#define Ww 96
#define COo 64
#define KK9 9
#define HW 9216           // 96*96
#define NPIX 73728        // 8*9216

// ---------------- scratch (device globals; no allocation allowed) ----------------
__device__ float g_xt[Nn * Hh * Ww * Cc];              // x transposed to NHWC
__device__ float g_offm[NPIX * 32];                    // per-pixel offsets + sigmoid(mask)
__device__ __align__(16) uint32_t g_wt[KK9 * 4096];    // per-tap [64co][64c] tf32 bits
__device__ __align__(16) uint32_t g_woff[KK9 * 2048];  // per-tap [32ch][64c] tf32 bits (27 real)

static __device__ __forceinline__ uint32_t f2tf32(float v) {
    uint32_t r;
    asm("cvt.rna.tf32.f32 %0, %1;" : "=r"(r) : "f"(v));
    return r;
}

static __device__ __forceinline__ void mma_tf32(float* d, const uint32_t* a, const uint32_t* b) {
    asm volatile("mma.sync.aligned.m16n8k8.row.col.f32.tf32.tf32.f32 "
                 "{%0,%1,%2,%3}, {%4,%5,%6,%7}, {%8,%9}, {%0,%1,%2,%3};"
                 : "+f"(d[0]), "+f"(d[1]), "+f"(d[2]), "+f"(d[3])
                 : "r"(a[0]), "r"(a[1]), "r"(a[2]), "r"(a[3]), "r"(b[0]), "r"(b[1]));
}

// ---------------- kernel 0: x NCHW -> NHWC (tiled transpose) ----------------
__global__ void k_transpose_x(const float* __restrict__ x) {
    __shared__ float tile[32][33];
    int z = blockIdx.z;
    int n = z / Hh;
    int y = z % Hh;
    int xb = blockIdx.x * 32;
    int cb = blockIdx.y * 32;
    int tx = threadIdx.x, ty = threadIdx.y;
#pragma unroll
    for (int k = 0; k < 4; k++) {
        int c = cb + ty + k * 8;
        tile[ty + k * 8][tx] = x[((n * Cc + c) * Hh + y) * Ww + xb + tx];
    }
    __syncthreads();
#pragma unroll
    for (int k = 0; k < 4; k++) {
        int xo = xb + ty + k * 8;
        g_xt[((n * Hh + y) * Ww + xo) * Cc + cb + tx] = tile[tx][ty + k * 8];
    }
}

// ---------------- kernel 0b: weight [co][c][3][3] -> g_wt[t][co][c] (tf32) ----------------
__global__ void k_transpose_w(const float* __restrict__ weight) {
    int i = blockIdx.x * 256 + threadIdx.x;   // t*4096 + co*64 + c
    if (i < KK9 * 4096) {
        int c = i & 63;
        int co = (i >> 6) & 63;
        int t = i >> 12;
        g_wt[i] = f2tf32(weight[(co * Cc + c) * KK9 + t]);
    }
}

// ---------------- kernel 0c: w_off [27][64][3][3] -> g_woff[t][32ch][c] (tf32, zero-pad) ----
__global__ void k_transpose_woff(const float* __restrict__ w_off) {
    int i = blockIdx.x * 256 + threadIdx.x;   // t*2048 + ch*64 + c
    if (i < KK9 * 2048) {
        int c = i & 63;
        int ch = (i >> 6) & 31;
        int t = i >> 11;
        g_woff[i] = (ch < 27) ? f2tf32(w_off[(ch * Cc + c) * KK9 + t]) : 0u;
    }
}

#define A_STRIDE 68

// ---------------- kernel 1: offset conv via tensor cores ----------------
// g_offm[p][ch] = sigmoid?(sum_{t,c} w_off[ch][c][t] * x[p@tap t][c] + b_off[ch])
// Block: 128 pix x 32 ch; 256 threads (8 warps); warp tile 32pix x 16ch.
#define OC_SMEM (128 * A_STRIDE * 4 + 32 * A_STRIDE * 4 + 128 * 8)

__global__ void __launch_bounds__(256, 4) k_offconv(const float* __restrict__ b_off) {
    extern __shared__ char base[];
    uint32_t* valS = (uint32_t*)base;                          // [128][68]
    uint32_t* wtS  = valS + 128 * A_STRIDE;                    // [32][68]
    int*      rowY = (int*)(wtS + 32 * A_STRIDE);              // [128]
    int*      rowX = rowY + 128;                               // [128]

    int tid = threadIdx.x;
    int wid = tid >> 5;
    int lane = tid & 31;
    int pix0 = blockIdx.x * 128;
    int nb = pix0 / HW;
    int rem0 = pix0 % HW;

    if (tid < 128) {
        int rem = rem0 + tid;
        rowY[tid] = rem / Ww;
        rowX[tid] = rem % Ww;
    }

    int wm = (wid & 3) * 32;
    int wn = (wid >> 2) * 16;
    int lg = lane >> 2;
    int lt = lane & 3;

    float acc[2][2][4];
#pragma unroll
    for (int mt = 0; mt < 2; mt++)
#pragma unroll
        for (int nt = 0; nt < 2; nt++)
#pragma unroll
            for (int r = 0; r < 4; r++) acc[mt][nt][r] = 0.f;
    __syncthreads();

    for (int t = 0; t < KK9; t++) {
        int ky = t / 3, kx = t % 3;
        // stage weights [32ch][64c] -> wtS
        {
            const uint4* gw = (const uint4*)(g_woff + t * 2048);
#pragma unroll
            for (int i = 0; i < 2; i++) {
                int e = tid + i * 256;
                uint4 v = gw[e];
                int ch = e >> 4;
                int c4 = (e & 15) << 2;
                *(uint4*)&wtS[ch * A_STRIDE + c4] = v;
            }
        }
        // fill valS[pl][c] from g_xt at integer tap (zero padding)
#pragma unroll
        for (int j = 0; j < 8; j++) {
            int idx = tid + j * 256;
            int pl = idx >> 4;
            int c4 = (idx & 15) << 2;
            int yy = rowY[pl] + ky - 1;
            int xx = rowX[pl] + kx - 1;
            uint4 o = make_uint4(0u, 0u, 0u, 0u);
            if ((unsigned)yy < Hh && (unsigned)xx < Ww) {
                float4 xv = *(const float4*)&g_xt[((nb * Hh + yy) * Ww + xx) * Cc + c4];
                o.x = f2tf32(xv.x); o.y = f2tf32(xv.y);
                o.z = f2tf32(xv.z); o.w = f2tf32(xv.w);
            }
            *(uint4*)&valS[pl * A_STRIDE + c4] = o;
        }
        __syncthreads();

#pragma unroll
        for (int kk = 0; kk < 8; kk++) {
            int k0 = kk * 8;
            uint32_t a[2][4];
#pragma unroll
            for (int mt = 0; mt < 2; mt++) {
                const uint32_t* ap = &valS[(wm + mt * 16 + lg) * A_STRIDE + k0 + lt];
                a[mt][0] = ap[0];
                a[mt][1] = ap[8 * A_STRIDE];
                a[mt][2] = ap[4];
                a[mt][3] = ap[8 * A_STRIDE + 4];
            }
            uint32_t b[2][2];
#pragma unroll
            for (int nt = 0; nt < 2; nt++) {
                const uint32_t* bp = &wtS[(wn + nt * 8 + lg) * A_STRIDE + k0 + lt];
                b[nt][0] = bp[0];
                b[nt][1] = bp[4];
            }
#pragma unroll
            for (int mt = 0; mt < 2; mt++)
#pragma unroll
                for (int nt = 0; nt < 2; nt++)
                    mma_tf32(acc[mt][nt], a[mt], b[nt]);
        }
        __syncthreads();
    }

    // epilogue: bias + sigmoid(mask), direct global stores
#pragma unroll
    for (int mt = 0; mt < 2; mt++)
#pragma unroll
        for (int nt = 0; nt < 2; nt++)
#pragma unroll
            for (int r = 0; r < 4; r++) {
                int pix = wm + mt * 16 + ((r >> 1) << 3) + lg;
                int ch = wn + nt * 8 + 2 * lt + (r & 1);
                if (ch < 27) {
                    float v = acc[mt][nt][r] + __ldg(&b_off[ch]);
                    if (ch >= 18) v = 1.f / (1.f + __expf(-v));
                    g_offm[(size_t)(pix0 + pix) * 32 + ch] = v;
                }
            }
}

// ---------------- kernel 2: fused bilinear-gather + mma.sync tf32 GEMM (v3) ----------------
// Block: 128pix x 64co; 512 threads (16 warps); warp tile 32pix x 16co.
// All 9 taps' bilinear metadata precomputed once per block.
#define O_STRIDE 132
#define SM_VAL  0
#define SM_WT   (128 * A_STRIDE * 4)                 // 34816
#define SM_ENTW (SM_WT + 64 * A_STRIDE * 4)          // 52224
#define SM_ENTB (SM_ENTW + 1152 * 16)                // 70656
#define SM_ENTD (SM_ENTB + 1152 * 4)                 // 75264
#define DEFORM_SMEM (SM_ENTD + 1152 * 4)             // 79872

__global__ void __launch_bounds__(512, 2) k_deform(const float* __restrict__ bias,
                                                   float* __restrict__ out) {
    extern __shared__ char base[];
    uint32_t* valS = (uint32_t*)(base + SM_VAL);
    uint32_t* wtS  = (uint32_t*)(base + SM_WT);
    float4*   entW = (float4*)(base + SM_ENTW);
    int*      entB = (int*)(base + SM_ENTB);
    int*      entD = (int*)(base + SM_ENTD);
    float*    outS = (float*)base;                   // epilogue overlay [64co][132]

    int tid = threadIdx.x;
    int wid = tid >> 5;
    int lane = tid & 31;
    int pix0 = blockIdx.x * 128;
    int nb = pix0 / HW;
    int rem0 = pix0 % HW;

    // ---- precompute all 9 taps' bilinear metadata ----
    for (int e = tid; e < KK9 * 128; e += 512) {
        int t = e >> 7;
        int pl = e & 127;
        int p = pix0 + pl;
        int rem = rem0 + pl;
        int y = rem / Ww;
        int x = rem % Ww;
        float dy = g_offm[(size_t)p * 32 + 2 * t];
        float dx = g_offm[(size_t)p * 32 + 2 * t + 1];
        float m = g_offm[(size_t)p * 32 + 18 + t];
        int ky = t / 3, kx = t % 3;
        float py = (float)(y + ky - 1) + dy;
        float px = (float)(x + kx - 1) + dx;
        float fy = floorf(py), fx = floorf(px);
        float ly = py - fy, lx = px - fx;
        int iy = (int)fy, ix = (int)fx;
        float hy0 = (iy >= 0 && iy < Hh) ? (1.f - ly) : 0.f;
        float hy1 = (iy >= -1 && iy < Hh - 1) ? ly : 0.f;
        float hx0 = (ix >= 0 && ix < Ww) ? (1.f - lx) : 0.f;
        float hx1 = (ix >= -1 && ix < Ww - 1) ? lx : 0.f;
        int iyc = min(max(iy, 0), Hh - 1);
        int ixc = min(max(ix, 0), Ww - 1);
        int ddy = (iy >= 0 && iy < Hh - 1) ? Ww * Cc : 0;
        int ddx = (ix >= 0 && ix < Ww - 1) ? Cc : 0;
        entB[e] = ((nb * Hh + iyc) * Ww + ixc) * Cc;
        entD[e] = ddx | (ddy << 16);
        entW[e] = make_float4(hy0 * hx0 * m, hy0 * hx1 * m, hy1 * hx0 * m, hy1 * hx1 * m);
    }

    int wm = (wid & 3) * 32;      // warp pixel base
    int wn = (wid >> 2) * 16;     // warp co base
    int lg = lane >> 2;
    int lt = lane & 3;

    float acc[2][2][4];
#pragma unroll
    for (int mt = 0; mt < 2; mt++)
#pragma unroll
        for (int nt = 0; nt < 2; nt++)
#pragma unroll
            for (int r = 0; r < 4; r++) acc[mt][nt][r] = 0.f;

    int cg = tid & 63;            // gather channel lane
    int q = tid >> 6;             // gather pixel phase (0..7)
    __syncthreads();

    for (int t = 0; t < KK9; t++) {
        // stage weights [64co][64c] -> wtS
        {
            const uint4* gw = (const uint4*)(g_wt + t * 4096);
#pragma unroll
            for (int i = 0; i < 2; i++) {
                int e = tid + i * 512;
                uint4 v = gw[e];
                int co = e >> 4;
                int c4 = (e & 15) << 2;
                *(uint4*)&wtS[co * A_STRIDE + c4] = v;
            }
        }
        // bilinear gather -> valS[pix][c] tf32
#pragma unroll 4
        for (int s = 0; s < 16; s++) {
            int pl = s * 8 + q;
            int e = t * 128 + pl;
            float4 w = entW[e];
            int gbase = entB[e] + cg;
            int dd = entD[e];
            int ddx = dd & 0xffff;
            int ddy = dd >> 16;
            float v = w.x * g_xt[gbase]
                    + w.y * g_xt[gbase + ddx]
                    + w.z * g_xt[gbase + ddy]
                    + w.w * g_xt[gbase + ddy + ddx];
            valS[pl * A_STRIDE + cg] = f2tf32(v);
        }
        __syncthreads();

        // tensor-core GEMM for this tap (K = 64, 8 k-steps)
#pragma unroll
        for (int kk = 0; kk < 8; kk++) {
            int k0 = kk * 8;
            uint32_t a[2][4];
#pragma unroll
            for (int mt = 0; mt < 2; mt++) {
                const uint32_t* ap = &valS[(wm + mt * 16 + lg) * A_STRIDE + k0 + lt];
                a[mt][0] = ap[0];
                a[mt][1] = ap[8 * A_STRIDE];
                a[mt][2] = ap[4];
                a[mt][3] = ap[8 * A_STRIDE + 4];
            }
            uint32_t b[2][2];
#pragma unroll
            for (int nt = 0; nt < 2; nt++) {
                const uint32_t* bp = &wtS[(wn + nt * 8 + lg) * A_STRIDE + k0 + lt];
                b[nt][0] = bp[0];
                b[nt][1] = bp[4];
            }
#pragma unroll
            for (int mt = 0; mt < 2; mt++)
#pragma unroll
                for (int nt = 0; nt < 2; nt++)
                    mma_tf32(acc[mt][nt], a[mt], b[nt]);
        }
        __syncthreads();
    }

    // epilogue: fragments -> smem [co][pix] -> coalesced NCHW stores
#pragma unroll
    for (int mt = 0; mt < 2; mt++)
#pragma unroll
        for (int nt = 0; nt < 2; nt++)
#pragma unroll
            for (int r = 0; r < 4; r++) {
                int pix = wm + mt * 16 + ((r >> 1) << 3) + lg;
                int co = wn + nt * 8 + 2 * lt + (r & 1);
                outS[co * O_STRIDE + pix] = acc[mt][nt][r];
            }
    __syncthreads();

#pragma unroll
    for (int i = 0; i < 4; i++) {
        int co = i * 16 + wid;
        int px = lane * 4;
        float4 v = *(const float4*)&outS[co * O_STRIDE + px];
        float bv = __ldg(&bias[co]);
        v.x += bv; v.y += bv; v.z += bv; v.w += bv;
        *(float4*)&out[((size_t)nb * COo + co) * HW + rem0 + px] = v;
    }
}

// ---------------- launch ----------------
extern "C" void kernel_launch(void* const* d_in, const int* in_sizes, int n_in,
                              void* d_out, int out_size) {
    const float* x      = (const float*)d_in[0];
    const float* w_off  = (const float*)d_in[1];
    const float* b_off  = (const float*)d_in[2];
    const float* weight = (const float*)d_in[3];
    const float* bias   = (const float*)d_in[4];
    float* out = (float*)d_out;

    static int attr_set = 0;
    if (!attr_set) {
        cudaFuncSetAttribute(k_deform, cudaFuncAttributeMaxDynamicSharedMemorySize, DEFORM_SMEM);
        cudaFuncSetAttribute(k_offconv, cudaFuncAttributeMaxDynamicSharedMemorySize, OC_SMEM);
        attr_set = 1;
    }

    k_transpose_x<<<dim3(3, 2, Nn * Hh), dim3(32, 8)>>>(x);
    k_transpose_w<<<144, 256>>>(weight);
    k_transpose_woff<<<72, 256>>>(w_off);
    k_offconv<<<NPIX / 128, 256, OC_SMEM>>>(b_off);
    k_deform<<<NPIX / 128, 512, DEFORM_SMEM>>>(bias, out);
}

// round 7
// speedup vs baseline: 2.0444x; 1.0132x over previous
#include <cuda_runtime.h>
#include <cuda_bf16.h>
#include <cstdint>

// Problem constants
#define Nn 8
#define Cc 64
#define Hh 96
#define Ww 96
#define COo 64
#define KK9 9
#define HW 9216           // 96*96
#define NPIX 73728        // 8*9216

// ---------------- scratch (device globals; no allocation allowed) ----------------
__device__ float g_xt[Nn * Hh * Ww * Cc];                 // x NHWC fp32 (deform gather)
__device__ __align__(16) uint32_t g_xtf[Nn * Hh * Ww * Cc];  // x NHWC tf32 bits (offconv A)
__device__ float g_offm[NPIX * 32];                       // per-pixel offsets + sigmoid(mask)
// fragment-major weights: [t][cog][nt][kk][lane][2]
__device__ __align__(16) uint32_t g_wtf[KK9 * 4 * 2 * 8 * 64];    // main conv  (36864)
__device__ __align__(16) uint32_t g_wofff[KK9 * 2 * 2 * 8 * 64];  // offset conv (18432)

static __device__ __forceinline__ uint32_t f2tf32(float v) {
    uint32_t r;
    asm("cvt.rna.tf32.f32 %0, %1;" : "=r"(r) : "f"(v));
    return r;
}

static __device__ __forceinline__ void mma_tf32(float* d, const uint32_t* a, const uint32_t* b) {
    asm volatile("mma.sync.aligned.m16n8k8.row.col.f32.tf32.tf32.f32 "
                 "{%0,%1,%2,%3}, {%4,%5,%6,%7}, {%8,%9}, {%0,%1,%2,%3};"
                 : "+f"(d[0]), "+f"(d[1]), "+f"(d[2]), "+f"(d[3])
                 : "r"(a[0]), "r"(a[1]), "r"(a[2]), "r"(a[3]), "r"(b[0]), "r"(b[1]));
}

// ---------------- kernel 0: x NCHW -> NHWC (fp32 + tf32 copies) ----------------
__global__ void k_transpose_x(const float* __restrict__ x) {
    __shared__ float tile[32][33];
    int z = blockIdx.z;
    int n = z / Hh;
    int y = z % Hh;
    int xb = blockIdx.x * 32;
    int cb = blockIdx.y * 32;
    int tx = threadIdx.x, ty = threadIdx.y;
#pragma unroll
    for (int k = 0; k < 4; k++) {
        int c = cb + ty + k * 8;
        tile[ty + k * 8][tx] = x[((n * Cc + c) * Hh + y) * Ww + xb + tx];
    }
    __syncthreads();
#pragma unroll
    for (int k = 0; k < 4; k++) {
        int xo = xb + ty + k * 8;
        float v = tile[tx][ty + k * 8];
        int idx = ((n * Hh + y) * Ww + xo) * Cc + cb + tx;
        g_xt[idx] = v;
        g_xtf[idx] = f2tf32(v);
    }
}

// ---------------- kernel 0b: weight -> fragment-major g_wtf ----------------
// idx = ((((t*4+cog)*2+nt)*8+kk)*32+lane)*2 + j
// co = cog*16 + nt*8 + (lane>>2);  c = kk*8 + (lane&3) + 4*j
__global__ void k_transpose_w(const float* __restrict__ weight) {
    int idx = blockIdx.x * 256 + threadIdx.x;
    if (idx < KK9 * 4096) {
        int j = idx & 1;
        int lane = (idx >> 1) & 31;
        int kk = (idx >> 6) & 7;
        int nt = (idx >> 9) & 1;
        int cog = (idx >> 10) & 3;
        int t = idx >> 12;
        int co = cog * 16 + nt * 8 + (lane >> 2);
        int c = kk * 8 + (lane & 3) + 4 * j;
        g_wtf[idx] = f2tf32(weight[(co * Cc + c) * KK9 + t]);
    }
}

// ---------------- kernel 0c: w_off -> fragment-major g_wofff (zero-pad ch>=27) ----------------
__global__ void k_transpose_woff(const float* __restrict__ w_off) {
    int idx = blockIdx.x * 256 + threadIdx.x;
    if (idx < KK9 * 2048) {
        int j = idx & 1;
        int lane = (idx >> 1) & 31;
        int kk = (idx >> 6) & 7;
        int nt = (idx >> 9) & 1;
        int cog = (idx >> 10) & 1;
        int t = idx >> 11;
        int ch = cog * 16 + nt * 8 + (lane >> 2);
        int c = kk * 8 + (lane & 3) + 4 * j;
        g_wofff[idx] = (ch < 27) ? f2tf32(w_off[(ch * Cc + c) * KK9 + t]) : 0u;
    }
}

#define A_STRIDE 68

// ---------------- kernel 1: offset conv via tensor cores (B from global frags) ----------------
// Block: 128 pix x 32 ch; 256 threads; warp tile 32pix x 16ch.
#define OC_SMEM (128 * A_STRIDE * 4 + 1152 * 4)

__global__ void __launch_bounds__(256, 4) k_offconv(const float* __restrict__ b_off) {
    extern __shared__ char base[];
    uint32_t* valS  = (uint32_t*)base;                 // [128][68]
    int*      obase = (int*)(valS + 128 * A_STRIDE);   // [9*128] gmem base or -1

    int tid = threadIdx.x;
    int wid = tid >> 5;
    int lane = tid & 31;
    int pix0 = blockIdx.x * 128;
    int nb = pix0 / HW;
    int rem0 = pix0 % HW;
    int cog = wid >> 2;

    // precompute all 9 taps' bases
    for (int e = tid; e < KK9 * 128; e += 256) {
        int t = e >> 7;
        int pl = e & 127;
        int rem = rem0 + pl;
        int yy = rem / Ww + t / 3 - 1;
        int xx = rem % Ww + t % 3 - 1;
        obase[e] = ((unsigned)yy < Hh && (unsigned)xx < Ww)
                 ? ((nb * Hh + yy) * Ww + xx) * Cc : -1;
    }

    int wm = (wid & 3) * 32;
    int lg = lane >> 2;
    int lt = lane & 3;

    float acc[2][2][4];
#pragma unroll
    for (int mt = 0; mt < 2; mt++)
#pragma unroll
        for (int nt = 0; nt < 2; nt++)
#pragma unroll
            for (int r = 0; r < 4; r++) acc[mt][nt][r] = 0.f;
    __syncthreads();

    for (int t = 0; t < KK9; t++) {
        // fill valS[pl][c] (pure uint4 copy of pre-converted tf32)
#pragma unroll
        for (int j = 0; j < 8; j++) {
            int idx = tid + j * 256;
            int pl = idx >> 4;
            int c4 = (idx & 15) << 2;
            int b = obase[t * 128 + pl];
            uint4 o = make_uint4(0u, 0u, 0u, 0u);
            if (b >= 0) o = *(const uint4*)&g_xtf[b + c4];
            *(uint4*)&valS[pl * A_STRIDE + c4] = o;
        }
        __syncthreads();

#pragma unroll
        for (int kk = 0; kk < 8; kk++) {
            int k0 = kk * 8;
            uint32_t a[2][4];
#pragma unroll
            for (int mt = 0; mt < 2; mt++) {
                const uint32_t* ap = &valS[(wm + mt * 16 + lg) * A_STRIDE + k0 + lt];
                a[mt][0] = ap[0];
                a[mt][1] = ap[8 * A_STRIDE];
                a[mt][2] = ap[4];
                a[mt][3] = ap[8 * A_STRIDE + 4];
            }
#pragma unroll
            for (int nt = 0; nt < 2; nt++) {
                uint2 bv = ((const uint2*)&g_wofff[(((t * 2 + cog) * 2 + nt) * 8 + kk) * 64])[lane];
                uint32_t b[2] = {bv.x, bv.y};
#pragma unroll
                for (int mt = 0; mt < 2; mt++)
                    mma_tf32(acc[mt][nt], a[mt], b);
            }
        }
        __syncthreads();
    }

    // epilogue: bias + sigmoid(mask)
#pragma unroll
    for (int mt = 0; mt < 2; mt++)
#pragma unroll
        for (int nt = 0; nt < 2; nt++)
#pragma unroll
            for (int r = 0; r < 4; r++) {
                int pix = wm + mt * 16 + ((r >> 1) << 3) + lg;
                int ch = cog * 16 + nt * 8 + 2 * lt + (r & 1);
                if (ch < 27) {
                    float v = acc[mt][nt][r] + __ldg(&b_off[ch]);
                    if (ch >= 18) v = 1.f / (1.f + __expf(-v));
                    g_offm[(size_t)(pix0 + pix) * 32 + ch] = v;
                }
            }
}

// ---------------- kernel 2: fused bilinear-gather + tf32 mma, 1-sync pipeline ----------------
// Block: 128pix x 64co; 512 threads (16 warps); warp tile 32pix x 16co.
// valS double-buffered; B fragments from global (fragment-major, L1-resident).
#define O_STRIDE 132
#define BUFW (128 * A_STRIDE)                         // words per val buffer
#define SM_ENTW (2 * BUFW * 4)                        // 69632
#define SM_ENTB (SM_ENTW + 1152 * 16)                 // 88064
#define SM_ENTD (SM_ENTB + 1152 * 4)                  // 92672
#define DEFORM_SMEM (SM_ENTD + 1152 * 4)              // 97280

__global__ void __launch_bounds__(512, 2) k_deform(const float* __restrict__ bias,
                                                   float* __restrict__ out) {
    extern __shared__ char base[];
    uint32_t* valS = (uint32_t*)base;                // [2][128][68]
    float4*   entW = (float4*)(base + SM_ENTW);
    int*      entB = (int*)(base + SM_ENTB);
    int*      entD = (int*)(base + SM_ENTD);
    float*    outS = (float*)base;                   // epilogue overlay [64co][132]

    int tid = threadIdx.x;
    int wid = tid >> 5;
    int lane = tid & 31;
    int pix0 = blockIdx.x * 128;
    int nb = pix0 / HW;
    int rem0 = pix0 % HW;

    // ---- precompute all 9 taps' bilinear metadata ----
    for (int e = tid; e < KK9 * 128; e += 512) {
        int t = e >> 7;
        int pl = e & 127;
        int p = pix0 + pl;
        int rem = rem0 + pl;
        int y = rem / Ww;
        int x = rem % Ww;
        float dy = g_offm[(size_t)p * 32 + 2 * t];
        float dx = g_offm[(size_t)p * 32 + 2 * t + 1];
        float m = g_offm[(size_t)p * 32 + 18 + t];
        int ky = t / 3, kx = t % 3;
        float py = (float)(y + ky - 1) + dy;
        float px = (float)(x + kx - 1) + dx;
        float fy = floorf(py), fx = floorf(px);
        float ly = py - fy, lx = px - fx;
        int iy = (int)fy, ix = (int)fx;
        float hy0 = (iy >= 0 && iy < Hh) ? (1.f - ly) : 0.f;
        float hy1 = (iy >= -1 && iy < Hh - 1) ? ly : 0.f;
        float hx0 = (ix >= 0 && ix < Ww) ? (1.f - lx) : 0.f;
        float hx1 = (ix >= -1 && ix < Ww - 1) ? lx : 0.f;
        int iyc = min(max(iy, 0), Hh - 1);
        int ixc = min(max(ix, 0), Ww - 1);
        int ddy = (iy >= 0 && iy < Hh - 1) ? Ww * Cc : 0;
        int ddx = (ix >= 0 && ix < Ww - 1) ? Cc : 0;
        entB[e] = ((nb * Hh + iyc) * Ww + ixc) * Cc;
        entD[e] = ddx | (ddy << 16);
        entW[e] = make_float4(hy0 * hx0 * m, hy0 * hx1 * m, hy1 * hx0 * m, hy1 * hx1 * m);
    }

    int wm = (wid & 3) * 32;      // warp pixel base
    int cog = wid >> 2;           // co group (16 co each)
    int lg = lane >> 2;
    int lt = lane & 3;

    float acc[2][2][4];
#pragma unroll
    for (int mt = 0; mt < 2; mt++)
#pragma unroll
        for (int nt = 0; nt < 2; nt++)
#pragma unroll
            for (int r = 0; r < 4; r++) acc[mt][nt][r] = 0.f;

    int cg = tid & 63;            // gather channel lane
    int q = tid >> 6;             // gather pixel phase (0..7)
    __syncthreads();              // metadata visible

    // ---- prologue gather: tap 0 -> buf 0 ----
    {
        uint32_t* buf = valS;
#pragma unroll 4
        for (int s = 0; s < 16; s++) {
            int pl = s * 8 + q;
            float4 w = entW[pl];
            int gbase = entB[pl] + cg;
            int dd = entD[pl];
            int ddx = dd & 0xffff;
            int ddy = dd >> 16;
            float v = w.x * g_xt[gbase]
                    + w.y * g_xt[gbase + ddx]
                    + w.z * g_xt[gbase + ddy]
                    + w.w * g_xt[gbase + ddy + ddx];
            buf[pl * A_STRIDE + cg] = f2tf32(v);
        }
    }
    __syncthreads();

    // ---- pipelined mainloop: mma(t) || gather(t+1), one sync per tap ----
    for (int t = 0; t < KK9; t++) {
        const uint32_t* cur = valS + (t & 1) * BUFW;
#pragma unroll
        for (int kk = 0; kk < 8; kk++) {
            int k0 = kk * 8;
            uint32_t a[2][4];
#pragma unroll
            for (int mt = 0; mt < 2; mt++) {
                const uint32_t* ap = &cur[(wm + mt * 16 + lg) * A_STRIDE + k0 + lt];
                a[mt][0] = ap[0];
                a[mt][1] = ap[8 * A_STRIDE];
                a[mt][2] = ap[4];
                a[mt][3] = ap[8 * A_STRIDE + 4];
            }
#pragma unroll
            for (int nt = 0; nt < 2; nt++) {
                uint2 bv = ((const uint2*)&g_wtf[(((t * 4 + cog) * 2 + nt) * 8 + kk) * 64])[lane];
                uint32_t b[2] = {bv.x, bv.y};
#pragma unroll
                for (int mt = 0; mt < 2; mt++)
                    mma_tf32(acc[mt][nt], a[mt], b);
            }
        }
        if (t < KK9 - 1) {
            uint32_t* nxt = valS + ((t + 1) & 1) * BUFW;
            int tb = (t + 1) * 128;
#pragma unroll 4
            for (int s = 0; s < 16; s++) {
                int pl = s * 8 + q;
                int e = tb + pl;
                float4 w = entW[e];
                int gbase = entB[e] + cg;
                int dd = entD[e];
                int ddx = dd & 0xffff;
                int ddy = dd >> 16;
                float v = w.x * g_xt[gbase]
                        + w.y * g_xt[gbase + ddx]
                        + w.z * g_xt[gbase + ddy]
                        + w.w * g_xt[gbase + ddy + ddx];
                nxt[pl * A_STRIDE + cg] = f2tf32(v);
            }
        }
        __syncthreads();
    }

    // ---- epilogue: fragments -> smem [co][pix] -> coalesced NCHW stores ----
#pragma unroll
    for (int mt = 0; mt < 2; mt++)
#pragma unroll
        for (int nt = 0; nt < 2; nt++)
#pragma unroll
            for (int r = 0; r < 4; r++) {
                int pix = wm + mt * 16 + ((r >> 1) << 3) + lg;
                int co = cog * 16 + nt * 8 + 2 * lt + (r & 1);
                outS[co * O_STRIDE + pix] = acc[mt][nt][r];
            }
    __syncthreads();

#pragma unroll
    for (int i = 0; i < 4; i++) {
        int co = i * 16 + wid;
        int px = lane * 4;
        float4 v = *(const float4*)&outS[co * O_STRIDE + px];
        float bv = __ldg(&bias[co]);
        v.x += bv; v.y += bv; v.z += bv; v.w += bv;
        *(float4*)&out[((size_t)nb * COo + co) * HW + rem0 + px] = v;
    }
}

// ---------------- launch ----------------
extern "C" void kernel_launch(void* const* d_in, const int* in_sizes, int n_in,
                              void* d_out, int out_size) {
    const float* x      = (const float*)d_in[0];
    const float* w_off  = (const float*)d_in[1];
    const float* b_off  = (const float*)d_in[2];
    const float* weight = (const float*)d_in[3];
    const float* bias   = (const float*)d_in[4];
    float* out = (float*)d_out;

    static int attr_set = 0;
    if (!attr_set) {
        cudaFuncSetAttribute(k_deform, cudaFuncAttributeMaxDynamicSharedMemorySize, DEFORM_SMEM);
        cudaFuncSetAttribute(k_offconv, cudaFuncAttributeMaxDynamicSharedMemorySize, OC_SMEM);
        attr_set = 1;
    }

    k_transpose_x<<<dim3(3, 2, Nn * Hh), dim3(32, 8)>>>(x);
    k_transpose_w<<<144, 256>>>(weight);
    k_transpose_woff<<<72, 256>>>(w_off);
    k_offconv<<<NPIX / 128, 256, OC_SMEM>>>(b_off);
    k_deform<<<NPIX / 128, 512, DEFORM_SMEM>>>(bias, out);
}

// round 8
// speedup vs baseline: 2.1860x; 1.0692x over previous
#include <cuda_runtime.h>
#include <cuda_bf16.h>
#include <cstdint>

// Problem constants
#define Nn 8
#define Cc 64
#define Hh 96
#define Ww 96
#define COo 64
#define KK9 9
#define HW 9216           // 96*96
#define NPIX 73728        // 8*9216

// ---------------- scratch (device globals; no allocation allowed) ----------------
__device__ float g_xt[Nn * Hh * Ww * Cc];                    // x NHWC fp32 (deform gather)
__device__ __align__(16) uint32_t g_xtf[Nn * Hh * Ww * Cc];  // x NHWC tf32 bits (offconv A)
// fragment-major weights
__device__ __align__(16) uint32_t g_wtf[KK9 * 4 * 2 * 8 * 64];    // main conv [t][cog4][nt2][kk][lane][2]
__device__ __align__(16) uint32_t g_wofff[KK9 * 2 * 2 * 8 * 64];  // off conv  [t][cog2][nt2][kk][lane][2]

static __device__ __forceinline__ uint32_t f2tf32(float v) {
    uint32_t r;
    asm("cvt.rna.tf32.f32 %0, %1;" : "=r"(r) : "f"(v));
    return r;
}
static __device__ __forceinline__ uint32_t smem_u32(const void* p) {
    uint32_t a;
    asm("{ .reg .u64 t; cvta.to.shared.u64 t, %1; cvt.u32.u64 %0, t; }" : "=r"(a) : "l"(p));
    return a;
}
static __device__ __forceinline__ void mma_tf32(float* d, const uint32_t* a, const uint32_t* b) {
    asm volatile("mma.sync.aligned.m16n8k8.row.col.f32.tf32.tf32.f32 "
                 "{%0,%1,%2,%3}, {%4,%5,%6,%7}, {%8,%9}, {%0,%1,%2,%3};"
                 : "+f"(d[0]), "+f"(d[1]), "+f"(d[2]), "+f"(d[3])
                 : "r"(a[0]), "r"(a[1]), "r"(a[2]), "r"(a[3]), "r"(b[0]), "r"(b[1]));
}
#define CP_ASYNC16(dst, src, sz) \
    asm volatile("cp.async.cg.shared.global [%0], [%1], 16, %2;" :: "r"(dst), "l"(src), "r"(sz) : "memory")
#define CP_COMMIT() asm volatile("cp.async.commit_group;" ::: "memory")
#define CP_WAIT(n)  asm volatile("cp.async.wait_group %0;" :: "n"(n) : "memory")

// ---------------- kernel 0: x NCHW -> NHWC (fp32 + tf32 copies) ----------------
__global__ void k_transpose_x(const float* __restrict__ x) {
    __shared__ float tile[32][33];
    int z = blockIdx.z;
    int n = z / Hh;
    int y = z % Hh;
    int xb = blockIdx.x * 32;
    int cb = blockIdx.y * 32;
    int tx = threadIdx.x, ty = threadIdx.y;
#pragma unroll
    for (int k = 0; k < 4; k++) {
        int c = cb + ty + k * 8;
        tile[ty + k * 8][tx] = x[((n * Cc + c) * Hh + y) * Ww + xb + tx];
    }
    __syncthreads();
#pragma unroll
    for (int k = 0; k < 4; k++) {
        int xo = xb + ty + k * 8;
        float v = tile[tx][ty + k * 8];
        int idx = ((n * Hh + y) * Ww + xo) * Cc + cb + tx;
        g_xt[idx] = v;
        g_xtf[idx] = f2tf32(v);
    }
}

// ---------------- kernel 0b: both weight arrays -> fragment-major ----------------
__global__ void k_prep_w(const float* __restrict__ weight, const float* __restrict__ w_off) {
    int gidx = blockIdx.x * 256 + threadIdx.x;
    if (gidx < KK9 * 4096) {
        int idx = gidx;
        int j = idx & 1;
        int lane = (idx >> 1) & 31;
        int kk = (idx >> 6) & 7;
        int nt = (idx >> 9) & 1;
        int cog = (idx >> 10) & 3;
        int t = idx >> 12;
        int co = cog * 16 + nt * 8 + (lane >> 2);
        int c = kk * 8 + (lane & 3) + 4 * j;
        g_wtf[idx] = f2tf32(weight[(co * Cc + c) * KK9 + t]);
    } else if (gidx < KK9 * 4096 + KK9 * 2048) {
        int idx = gidx - KK9 * 4096;
        int j = idx & 1;
        int lane = (idx >> 1) & 31;
        int kk = (idx >> 6) & 7;
        int nt = (idx >> 9) & 1;
        int cog = (idx >> 10) & 1;
        int t = idx >> 11;
        int ch = cog * 16 + nt * 8 + (lane >> 2);
        int c = kk * 8 + (lane & 3) + 4 * j;
        g_wofff[idx] = (ch < 27) ? f2tf32(w_off[(ch * Cc + c) * KK9 + t]) : 0u;
    }
}

// ---------------- fused kernel: offconv (TC) -> metadata -> deform (TC) ----------------
#define A_STRIDE 68
#define O_STRIDE 132
#define BUFW (128 * A_STRIDE)                  // words per val buffer
#define SM_ENTW (2 * BUFW * 4)                 // 69632
#define SM_ENTB (SM_ENTW + 1152 * 16)          // 88064  (obase overlays here)
#define SM_ENTD (SM_ENTB + 1152 * 4)           // 92672
#define SM_OFFM (SM_ENTD + 1152 * 4)           // 97280
#define FUSED_SMEM (SM_OFFM + 128 * 28 * 4)    // 111616

__global__ void __launch_bounds__(512, 2) k_fused(const float* __restrict__ b_off,
                                                  const float* __restrict__ bias,
                                                  float* __restrict__ out) {
    extern __shared__ char base[];
    uint32_t* valS = (uint32_t*)base;                // [2][128][68]
    float4*   entW = (float4*)(base + SM_ENTW);
    int*      entB = (int*)(base + SM_ENTB);
    int*      entD = (int*)(base + SM_ENTD);
    int*      obase = entB;                          // overlay (dead before entB written)
    float*    offmS = (float*)(base + SM_OFFM);      // [128][28]
    float*    outS = (float*)base;                   // epilogue overlay [64co][132]
    uint32_t  valS_sm = smem_u32(valS);

    int tid = threadIdx.x;
    int wid = tid >> 5;
    int lane = tid & 31;
    int pix0 = blockIdx.x * 128;
    int nb = pix0 / HW;
    int rem0 = pix0 % HW;
    int lg = lane >> 2;
    int lt = lane & 3;

    // ============ phase A: offset conv (128pix x 32ch, warp tile 16pix x 16ch) ============
    // obase for all 9 taps
    for (int e = tid; e < KK9 * 128; e += 512) {
        int t = e >> 7;
        int pl = e & 127;
        int rem = rem0 + pl;
        int yy = rem / Ww + t / 3 - 1;
        int xx = rem % Ww + t % 3 - 1;
        obase[e] = ((unsigned)yy < Hh && (unsigned)xx < Ww)
                 ? ((nb * Hh + yy) * Ww + xx) * Cc : -1;
    }
    __syncthreads();

    int wmA = (wid & 7) * 16;     // warp pixel base (phase A)
    int cogA = wid >> 3;          // ch group (16 ch)

    float accA[2][4];
#pragma unroll
    for (int nt = 0; nt < 2; nt++)
#pragma unroll
        for (int r = 0; r < 4; r++) accA[nt][r] = 0.f;

    // async fill of tap tt into buffer b
    auto fillA = [&](int tt, int b) {
        uint32_t dbase = valS_sm + b * (BUFW * 4);
#pragma unroll
        for (int j = 0; j < 4; j++) {
            int idx = tid + j * 512;
            int pl = idx >> 4;
            int c4 = (idx & 15) << 2;
            int gb = obase[tt * 128 + pl];
            const uint32_t* src = &g_xtf[(gb < 0 ? 0 : gb) + c4];
            CP_ASYNC16(dbase + (pl * A_STRIDE + c4) * 4, src, (gb < 0) ? 0 : 16);
        }
        CP_COMMIT();
    };

    fillA(0, 0);
    for (int t = 0; t < KK9; t++) {
        if (t < KK9 - 1) {
            fillA(t + 1, (t + 1) & 1);
            CP_WAIT(1);
        } else {
            CP_WAIT(0);
        }
        __syncthreads();
        const uint32_t* cur = valS + (t & 1) * BUFW;
#pragma unroll
        for (int kk = 0; kk < 8; kk++) {
            int k0 = kk * 8;
            const uint32_t* ap = &cur[(wmA + lg) * A_STRIDE + k0 + lt];
            uint32_t a[4] = {ap[0], ap[8 * A_STRIDE], ap[4], ap[8 * A_STRIDE + 4]};
#pragma unroll
            for (int nt = 0; nt < 2; nt++) {
                uint2 bv = ((const uint2*)&g_wofff[(((t * 2 + cogA) * 2 + nt) * 8 + kk) * 64])[lane];
                uint32_t b[2] = {bv.x, bv.y};
                mma_tf32(accA[nt], a, b);
            }
        }
        __syncthreads();   // protect buffer before next overwrite
    }

    // phase A epilogue -> offmS (bias + sigmoid on mask chans)
#pragma unroll
    for (int nt = 0; nt < 2; nt++)
#pragma unroll
        for (int r = 0; r < 4; r++) {
            int pix = wmA + ((r >> 1) << 3) + lg;
            int ch = cogA * 16 + nt * 8 + 2 * lt + (r & 1);
            if (ch < 27) {
                float v = accA[nt][r] + __ldg(&b_off[ch]);
                if (ch >= 18) v = 1.f / (1.f + __expf(-v));
                offmS[pix * 28 + ch] = v;
            }
        }
    __syncthreads();

    // ============ metadata: bilinear coefficients for all 9 taps ============
    for (int e = tid; e < KK9 * 128; e += 512) {
        int t = e >> 7;
        int pl = e & 127;
        int rem = rem0 + pl;
        int y = rem / Ww;
        int x = rem % Ww;
        float dy = offmS[pl * 28 + 2 * t];
        float dx = offmS[pl * 28 + 2 * t + 1];
        float m = offmS[pl * 28 + 18 + t];
        int ky = t / 3, kx = t % 3;
        float py = (float)(y + ky - 1) + dy;
        float px = (float)(x + kx - 1) + dx;
        float fy = floorf(py), fx = floorf(px);
        float ly = py - fy, lx = px - fx;
        int iy = (int)fy, ix = (int)fx;
        float hy0 = (iy >= 0 && iy < Hh) ? (1.f - ly) : 0.f;
        float hy1 = (iy >= -1 && iy < Hh - 1) ? ly : 0.f;
        float hx0 = (ix >= 0 && ix < Ww) ? (1.f - lx) : 0.f;
        float hx1 = (ix >= -1 && ix < Ww - 1) ? lx : 0.f;
        int iyc = min(max(iy, 0), Hh - 1);
        int ixc = min(max(ix, 0), Ww - 1);
        int ddy = (iy >= 0 && iy < Hh - 1) ? Ww * Cc : 0;
        int ddx = (ix >= 0 && ix < Ww - 1) ? Cc : 0;
        entB[e] = ((nb * Hh + iyc) * Ww + ixc) * Cc;   // overwrites obase (dead)
        entD[e] = ddx | (ddy << 16);
        entW[e] = make_float4(hy0 * hx0 * m, hy0 * hx1 * m, hy1 * hx0 * m, hy1 * hx1 * m);
    }

    // ============ phase B: deform (128pix x 64co, warp tile 32pix x 16co) ============
    int wm = (wid & 3) * 32;
    int cog = wid >> 2;
    int cg = tid & 63;            // gather channel lane
    int q = tid >> 6;             // gather pixel phase (0..7)

    float acc[2][2][4];
#pragma unroll
    for (int mt = 0; mt < 2; mt++)
#pragma unroll
        for (int nt = 0; nt < 2; nt++)
#pragma unroll
            for (int r = 0; r < 4; r++) acc[mt][nt][r] = 0.f;
    __syncthreads();              // metadata visible, valS free

    // prologue gather: tap 0 -> buf 0
#pragma unroll 4
    for (int s = 0; s < 16; s++) {
        int pl = s * 8 + q;
        float4 w = entW[pl];
        int gbase = entB[pl] + cg;
        int dd = entD[pl];
        int ddx = dd & 0xffff;
        int ddy = dd >> 16;
        float v = w.x * g_xt[gbase]
                + w.y * g_xt[gbase + ddx]
                + w.z * g_xt[gbase + ddy]
                + w.w * g_xt[gbase + ddy + ddx];
        valS[pl * A_STRIDE + cg] = f2tf32(v);
    }
    __syncthreads();

    for (int t = 0; t < KK9; t++) {
        const uint32_t* cur = valS + (t & 1) * BUFW;
#pragma unroll
        for (int kk = 0; kk < 8; kk++) {
            int k0 = kk * 8;
            uint32_t a[2][4];
#pragma unroll
            for (int mt = 0; mt < 2; mt++) {
                const uint32_t* ap = &cur[(wm + mt * 16 + lg) * A_STRIDE + k0 + lt];
                a[mt][0] = ap[0];
                a[mt][1] = ap[8 * A_STRIDE];
                a[mt][2] = ap[4];
                a[mt][3] = ap[8 * A_STRIDE + 4];
            }
#pragma unroll
            for (int nt = 0; nt < 2; nt++) {
                uint2 bv = ((const uint2*)&g_wtf[(((t * 4 + cog) * 2 + nt) * 8 + kk) * 64])[lane];
                uint32_t b[2] = {bv.x, bv.y};
#pragma unroll
                for (int mt = 0; mt < 2; mt++)
                    mma_tf32(acc[mt][nt], a[mt], b);
            }
        }
        if (t < KK9 - 1) {
            uint32_t* nxt = valS + ((t + 1) & 1) * BUFW;
            int tb = (t + 1) * 128;
#pragma unroll 4
            for (int s = 0; s < 16; s++) {
                int pl = s * 8 + q;
                int e = tb + pl;
                float4 w = entW[e];
                int gbase = entB[e] + cg;
                int dd = entD[e];
                int ddx = dd & 0xffff;
                int ddy = dd >> 16;
                float v = w.x * g_xt[gbase]
                        + w.y * g_xt[gbase + ddx]
                        + w.z * g_xt[gbase + ddy]
                        + w.w * g_xt[gbase + ddy + ddx];
                nxt[pl * A_STRIDE + cg] = f2tf32(v);
            }
        }
        __syncthreads();
    }

    // epilogue: fragments -> smem [co][pix] -> coalesced NCHW stores
#pragma unroll
    for (int mt = 0; mt < 2; mt++)
#pragma unroll
        for (int nt = 0; nt < 2; nt++)
#pragma unroll
            for (int r = 0; r < 4; r++) {
                int pix = wm + mt * 16 + ((r >> 1) << 3) + lg;
                int co = cog * 16 + nt * 8 + 2 * lt + (r & 1);
                outS[co * O_STRIDE + pix] = acc[mt][nt][r];
            }
    __syncthreads();

#pragma unroll
    for (int i = 0; i < 4; i++) {
        int co = i * 16 + wid;
        int px = lane * 4;
        float4 v = *(const float4*)&outS[co * O_STRIDE + px];
        float bv = __ldg(&bias[co]);
        v.x += bv; v.y += bv; v.z += bv; v.w += bv;
        *(float4*)&out[((size_t)nb * COo + co) * HW + rem0 + px] = v;
    }
}

// ---------------- launch ----------------
extern "C" void kernel_launch(void* const* d_in, const int* in_sizes, int n_in,
                              void* d_out, int out_size) {
    const float* x      = (const float*)d_in[0];
    const float* w_off  = (const float*)d_in[1];
    const float* b_off  = (const float*)d_in[2];
    const float* weight = (const float*)d_in[3];
    const float* bias   = (const float*)d_in[4];
    float* out = (float*)d_out;

    static int attr_set = 0;
    if (!attr_set) {
        cudaFuncSetAttribute(k_fused, cudaFuncAttributeMaxDynamicSharedMemorySize, FUSED_SMEM);
        attr_set = 1;
    }

    k_transpose_x<<<dim3(3, 2, Nn * Hh), dim3(32, 8)>>>(x);
    k_prep_w<<<(KK9 * 4096 + KK9 * 2048 + 255) / 256, 256>>>(weight, w_off);
    k_fused<<<NPIX / 128, 512, FUSED_SMEM>>>(b_off, bias, out);
}

// round 9
// speedup vs baseline: 2.3950x; 1.0956x over previous
#include <cuda_runtime.h>
#include <cuda_bf16.h>
#include <cstdint>

// Problem constants
#define Nn 8
#define Cc 64
#define Hh 96
#define Ww 96
#define COo 64
#define KK9 9
#define HW 9216           // 96*96
#define NPIX 73728        // 8*9216

// ---------------- scratch (device globals; no allocation allowed) ----------------
// x NHWC, tf32 bits, channels PERMUTED within 8-groups: pos = (c&~7) | ((c&3)<<1) | ((c>>2)&1)
__device__ __align__(16) uint32_t g_xtf[Nn * Hh * Ww * Cc];
// fragment-major weights, per-k-step uint4: [t][cog][kk][lane][nt][j]
__device__ __align__(16) uint32_t g_wtf[KK9 * 4 * 8 * 32 * 4];    // main conv (36864)
__device__ __align__(16) uint32_t g_wofff[KK9 * 2 * 8 * 32 * 4];  // off conv  (18432)

static __device__ __forceinline__ uint32_t f2tf32(float v) {
    uint32_t r;
    asm("cvt.rna.tf32.f32 %0, %1;" : "=r"(r) : "f"(v));
    return r;
}
static __device__ __forceinline__ uint32_t smem_u32(const void* p) {
    uint32_t a;
    asm("{ .reg .u64 t; cvta.to.shared.u64 t, %1; cvt.u32.u64 %0, t; }" : "=r"(a) : "l"(p));
    return a;
}
static __device__ __forceinline__ void mma_tf32(float* d, const uint32_t* a, const uint32_t* b) {
    asm volatile("mma.sync.aligned.m16n8k8.row.col.f32.tf32.tf32.f32 "
                 "{%0,%1,%2,%3}, {%4,%5,%6,%7}, {%8,%9}, {%0,%1,%2,%3};"
                 : "+f"(d[0]), "+f"(d[1]), "+f"(d[2]), "+f"(d[3])
                 : "r"(a[0]), "r"(a[1]), "r"(a[2]), "r"(a[3]), "r"(b[0]), "r"(b[1]));
}
#define CP_ASYNC16(dst, src, sz) \
    asm volatile("cp.async.cg.shared.global [%0], [%1], 16, %2;" :: "r"(dst), "l"(src), "r"(sz) : "memory")
#define CP_COMMIT() asm volatile("cp.async.commit_group;" ::: "memory")
#define CP_WAIT(n)  asm volatile("cp.async.wait_group %0;" :: "n"(n) : "memory")

// ---------------- kernel 0: x NCHW -> NHWC tf32 (channel-permuted) ----------------
__global__ void k_transpose_x(const float* __restrict__ x) {
    __shared__ float tile[32][33];
    int z = blockIdx.z;
    int n = z / Hh;
    int y = z % Hh;
    int xb = blockIdx.x * 32;
    int cb = blockIdx.y * 32;
    int tx = threadIdx.x, ty = threadIdx.y;
#pragma unroll
    for (int k = 0; k < 4; k++) {
        int c = cb + ty + k * 8;
        tile[ty + k * 8][tx] = x[((n * Cc + c) * Hh + y) * Ww + xb + tx];
    }
    __syncthreads();
    int c = cb + tx;
    int s = (c & 56) | ((c & 3) << 1) | ((c >> 2) & 1);   // permuted position
#pragma unroll
    for (int k = 0; k < 4; k++) {
        int xo = xb + ty + k * 8;
        g_xtf[((n * Hh + y) * Ww + xo) * Cc + s] = f2tf32(tile[tx][ty + k * 8]);
    }
}

// ---------------- kernel 0b: both weight arrays -> fragment-major (uint4/k-step) ----------------
__global__ void k_prep_w(const float* __restrict__ weight, const float* __restrict__ w_off) {
    int gidx = blockIdx.x * 256 + threadIdx.x;
    if (gidx < KK9 * 4096) {
        int idx = gidx;
        int j = idx & 1;
        int nt = (idx >> 1) & 1;
        int lane = (idx >> 2) & 31;
        int kk = (idx >> 7) & 7;
        int cog = (idx >> 10) & 3;
        int t = idx >> 12;
        int co = cog * 16 + nt * 8 + (lane >> 2);
        int c = kk * 8 + (lane & 3) + 4 * j;
        g_wtf[idx] = f2tf32(weight[(co * Cc + c) * KK9 + t]);
    } else if (gidx < KK9 * 4096 + KK9 * 2048) {
        int idx = gidx - KK9 * 4096;
        int j = idx & 1;
        int nt = (idx >> 1) & 1;
        int lane = (idx >> 2) & 31;
        int kk = (idx >> 7) & 7;
        int cog = (idx >> 10) & 1;
        int t = idx >> 11;
        int ch = cog * 16 + nt * 8 + (lane >> 2);
        int c = kk * 8 + (lane & 3) + 4 * j;
        g_wofff[idx] = (ch < 27) ? f2tf32(w_off[(ch * Cc + c) * KK9 + t]) : 0u;
    }
}

// ---------------- fused kernel: offconv (TC) -> metadata -> deform (TC) ----------------
#define A_STRIDE 72                            // 72 ≡ 8 (mod 32): conflict-free LDS.64 frags
#define O_STRIDE 132
#define BUFW (128 * A_STRIDE)                  // 9216 words per val buffer
#define SM_ENTW (2 * BUFW * 4)                 // 73728
#define SM_ENTB (SM_ENTW + 1152 * 16)          // 92160  (obase overlays here)
#define SM_ENTD (SM_ENTB + 1152 * 4)           // 96768
#define FUSED_SMEM (SM_ENTD + 1152 * 4)        // 101376

__global__ void __launch_bounds__(512, 2) k_fused(const float* __restrict__ b_off,
                                                  const float* __restrict__ bias,
                                                  float* __restrict__ out) {
    extern __shared__ char base[];
    uint32_t* valS = (uint32_t*)base;                // [2][128][72]
    float4*   entW = (float4*)(base + SM_ENTW);
    int*      entB = (int*)(base + SM_ENTB);
    int*      entD = (int*)(base + SM_ENTD);
    int*      obase = entB;                          // overlay (dead before entB written)
    float*    offmS = (float*)base;                  // [128][28] overlay (written after phase A)
    float*    outS = (float*)base;                   // epilogue overlay [64co][132]
    uint32_t  valS_sm = smem_u32(valS);
    const float* xtf = (const float*)g_xtf;

    int tid = threadIdx.x;
    int wid = tid >> 5;
    int lane = tid & 31;
    int pix0 = blockIdx.x * 128;
    int nb = pix0 / HW;
    int rem0 = pix0 % HW;
    int lg = lane >> 2;
    int lt = lane & 3;

    // ============ phase A: offset conv (128pix x 32ch, warp tile 16pix x 16ch) ============
    for (int e = tid; e < KK9 * 128; e += 512) {
        int t = e >> 7;
        int pl = e & 127;
        int rem = rem0 + pl;
        int yy = rem / Ww + t / 3 - 1;
        int xx = rem % Ww + t % 3 - 1;
        obase[e] = ((unsigned)yy < Hh && (unsigned)xx < Ww)
                 ? ((nb * Hh + yy) * Ww + xx) * Cc : -1;
    }
    __syncthreads();

    int wmA = (wid & 7) * 16;     // warp pixel base (phase A)
    int cogA = wid >> 3;          // ch group (16 ch)

    float accA[2][4];
#pragma unroll
    for (int nt = 0; nt < 2; nt++)
#pragma unroll
        for (int r = 0; r < 4; r++) accA[nt][r] = 0.f;

    auto fillA = [&](int tt, int b) {
        uint32_t dbase = valS_sm + b * (BUFW * 4);
#pragma unroll
        for (int j = 0; j < 4; j++) {
            int idx = tid + j * 512;
            int pl = idx >> 4;
            int c4 = (idx & 15) << 2;
            int gb = obase[tt * 128 + pl];
            const uint32_t* src = &g_xtf[(gb < 0 ? 0 : gb) + c4];
            CP_ASYNC16(dbase + (pl * A_STRIDE + c4) * 4, src, (gb < 0) ? 0 : 16);
        }
        CP_COMMIT();
    };

    fillA(0, 0);
    for (int t = 0; t < KK9; t++) {
        if (t < KK9 - 1) {
            fillA(t + 1, (t + 1) & 1);
            CP_WAIT(1);
        } else {
            CP_WAIT(0);
        }
        __syncthreads();
        const uint32_t* cur = valS + (t & 1) * BUFW;
#pragma unroll
        for (int kk = 0; kk < 8; kk++) {
            int k0 = kk * 8 + 2 * lt;
            uint2 p0 = *(const uint2*)&cur[(wmA + lg) * A_STRIDE + k0];
            uint2 p1 = *(const uint2*)&cur[(wmA + 8 + lg) * A_STRIDE + k0];
            uint32_t a[4] = {p0.x, p1.x, p0.y, p1.y};
            uint4 bv = ((const uint4*)&g_wofff[((t * 2 + cogA) * 8 + kk) * 128])[lane];
            uint32_t b0[2] = {bv.x, bv.y};
            uint32_t b1[2] = {bv.z, bv.w};
            mma_tf32(accA[0], a, b0);
            mma_tf32(accA[1], a, b1);
        }
        __syncthreads();
    }

    // phase A epilogue -> offmS (overlays buf0; loop is done)
#pragma unroll
    for (int nt = 0; nt < 2; nt++)
#pragma unroll
        for (int r = 0; r < 4; r++) {
            int pix = wmA + ((r >> 1) << 3) + lg;
            int ch = cogA * 16 + nt * 8 + 2 * lt + (r & 1);
            if (ch < 27) {
                float v = accA[nt][r] + __ldg(&b_off[ch]);
                if (ch >= 18) v = 1.f / (1.f + __expf(-v));
                offmS[pix * 28 + ch] = v;
            }
        }
    __syncthreads();

    // ============ metadata: bilinear coefficients for all 9 taps ============
    for (int e = tid; e < KK9 * 128; e += 512) {
        int t = e >> 7;
        int pl = e & 127;
        int rem = rem0 + pl;
        int y = rem / Ww;
        int x = rem % Ww;
        float dy = offmS[pl * 28 + 2 * t];
        float dx = offmS[pl * 28 + 2 * t + 1];
        float m = offmS[pl * 28 + 18 + t];
        int ky = t / 3, kx = t % 3;
        float py = (float)(y + ky - 1) + dy;
        float px = (float)(x + kx - 1) + dx;
        float fy = floorf(py), fx = floorf(px);
        float ly = py - fy, lx = px - fx;
        int iy = (int)fy, ix = (int)fx;
        float hy0 = (iy >= 0 && iy < Hh) ? (1.f - ly) : 0.f;
        float hy1 = (iy >= -1 && iy < Hh - 1) ? ly : 0.f;
        float hx0 = (ix >= 0 && ix < Ww) ? (1.f - lx) : 0.f;
        float hx1 = (ix >= -1 && ix < Ww - 1) ? lx : 0.f;
        int iyc = min(max(iy, 0), Hh - 1);
        int ixc = min(max(ix, 0), Ww - 1);
        int ddy = (iy >= 0 && iy < Hh - 1) ? Ww * Cc : 0;
        int ddx = (ix >= 0 && ix < Ww - 1) ? Cc : 0;
        entB[e] = ((nb * Hh + iyc) * Ww + ixc) * Cc;   // overwrites obase (dead)
        entD[e] = ddx | (ddy << 16);
        entW[e] = make_float4(hy0 * hx0 * m, hy0 * hx1 * m, hy1 * hx0 * m, hy1 * hx1 * m);
    }

    // ============ phase B: deform (128pix x 64co, warp tile 32pix x 16co) ============
    int wm = (wid & 3) * 32;
    int cog = wid >> 2;
    int cg = tid & 63;            // gather channel position
    int q = tid >> 6;             // gather pixel phase (0..7)

    float acc[2][2][4];
#pragma unroll
    for (int mt = 0; mt < 2; mt++)
#pragma unroll
        for (int nt = 0; nt < 2; nt++)
#pragma unroll
            for (int r = 0; r < 4; r++) acc[mt][nt][r] = 0.f;
    __syncthreads();              // metadata visible; offmS/valS free

    // prologue gather: tap 0 -> buf 0
#pragma unroll 4
    for (int s = 0; s < 16; s++) {
        int pl = s * 8 + q;
        float4 w = entW[pl];
        int gbase = entB[pl] + cg;
        int dd = entD[pl];
        int ddx = dd & 0xffff;
        int ddy = dd >> 16;
        float v = w.x * xtf[gbase]
                + w.y * xtf[gbase + ddx]
                + w.z * xtf[gbase + ddy]
                + w.w * xtf[gbase + ddy + ddx];
        valS[pl * A_STRIDE + cg] = f2tf32(v);
    }
    __syncthreads();

    for (int t = 0; t < KK9; t++) {
        const uint32_t* cur = valS + (t & 1) * BUFW;
#pragma unroll
        for (int kk = 0; kk < 8; kk++) {
            int k0 = kk * 8 + 2 * lt;
            uint32_t a[2][4];
#pragma unroll
            for (int mt = 0; mt < 2; mt++) {
                uint2 p0 = *(const uint2*)&cur[(wm + mt * 16 + lg) * A_STRIDE + k0];
                uint2 p1 = *(const uint2*)&cur[(wm + mt * 16 + 8 + lg) * A_STRIDE + k0];
                a[mt][0] = p0.x; a[mt][1] = p1.x; a[mt][2] = p0.y; a[mt][3] = p1.y;
            }
            uint4 bv = ((const uint4*)&g_wtf[((t * 4 + cog) * 8 + kk) * 128])[lane];
            uint32_t b0[2] = {bv.x, bv.y};
            uint32_t b1[2] = {bv.z, bv.w};
#pragma unroll
            for (int mt = 0; mt < 2; mt++) {
                mma_tf32(acc[mt][0], a[mt], b0);
                mma_tf32(acc[mt][1], a[mt], b1);
            }
        }
        if (t < KK9 - 1) {
            uint32_t* nxt = valS + ((t + 1) & 1) * BUFW;
            int tb = (t + 1) * 128;
#pragma unroll 4
            for (int s = 0; s < 16; s++) {
                int pl = s * 8 + q;
                int e = tb + pl;
                float4 w = entW[e];
                int gbase = entB[e] + cg;
                int dd = entD[e];
                int ddx = dd & 0xffff;
                int ddy = dd >> 16;
                float v = w.x * xtf[gbase]
                        + w.y * xtf[gbase + ddx]
                        + w.z * xtf[gbase + ddy]
                        + w.w * xtf[gbase + ddy + ddx];
                nxt[pl * A_STRIDE + cg] = f2tf32(v);
            }
        }
        __syncthreads();
    }

    // epilogue: fragments -> smem [co][pix] -> coalesced NCHW stores
#pragma unroll
    for (int mt = 0; mt < 2; mt++)
#pragma unroll
        for (int nt = 0; nt < 2; nt++)
#pragma unroll
            for (int r = 0; r < 4; r++) {
                int pix = wm + mt * 16 + ((r >> 1) << 3) + lg;
                int co = cog * 16 + nt * 8 + 2 * lt + (r & 1);
                outS[co * O_STRIDE + pix] = acc[mt][nt][r];
            }
    __syncthreads();

#pragma unroll
    for (int i = 0; i < 4; i++) {
        int co = i * 16 + wid;
        int px = lane * 4;
        float4 v = *(const float4*)&outS[co * O_STRIDE + px];
        float bv = __ldg(&bias[co]);
        v.x += bv; v.y += bv; v.z += bv; v.w += bv;
        *(float4*)&out[((size_t)nb * COo + co) * HW + rem0 + px] = v;
    }
}

// ---------------- launch ----------------
extern "C" void kernel_launch(void* const* d_in, const int* in_sizes, int n_in,
                              void* d_out, int out_size) {
    const float* x      = (const float*)d_in[0];
    const float* w_off  = (const float*)d_in[1];
    const float* b_off  = (const float*)d_in[2];
    const float* weight = (const float*)d_in[3];
    const float* bias   = (const float*)d_in[4];
    float* out = (float*)d_out;

    static int attr_set = 0;
    if (!attr_set) {
        cudaFuncSetAttribute(k_fused, cudaFuncAttributeMaxDynamicSharedMemorySize, FUSED_SMEM);
        attr_set = 1;
    }

    k_transpose_x<<<dim3(3, 2, Nn * Hh), dim3(32, 8)>>>(x);
    k_prep_w<<<(KK9 * 4096 + KK9 * 2048 + 255) / 256, 256>>>(weight, w_off);
    k_fused<<<NPIX / 128, 512, FUSED_SMEM>>>(b_off, bias, out);
}

// round 10
// speedup vs baseline: 3.0949x; 1.2922x over previous
#include <cuda_runtime.h>
#include <cuda_bf16.h>
#include <cstdint>

// Problem constants
#define Nn 8
#define Cc 64
#define Hh 96
#define Ww 96
#define COo 64
#define KK9 9
#define HW 9216           // 96*96
#define NPIX 73728        // 8*9216

// ---------------- scratch (device globals; no allocation allowed) ----------------
// x NHWC, tf32 bits, channels PERMUTED within 8-groups: pos = (c&~7) | ((c&3)<<1) | ((c>>2)&1)
__device__ __align__(16) uint32_t g_xtf[Nn * Hh * Ww * Cc];
// fragment-major weights, per-k-step uint4: [t][cog][kk][lane][nt][j]
__device__ __align__(16) uint32_t g_wtf[KK9 * 4 * 8 * 32 * 4];    // main conv (36864)
__device__ __align__(16) uint32_t g_wofff[KK9 * 2 * 8 * 32 * 4];  // off conv  (18432)

static __device__ __forceinline__ uint32_t f2tf32(float v) {
    uint32_t r;
    asm("cvt.rna.tf32.f32 %0, %1;" : "=r"(r) : "f"(v));
    return r;
}
static __device__ __forceinline__ uint32_t smem_u32(const void* p) {
    uint32_t a;
    asm("{ .reg .u64 t; cvta.to.shared.u64 t, %1; cvt.u32.u64 %0, t; }" : "=r"(a) : "l"(p));
    return a;
}
static __device__ __forceinline__ void mma_tf32(float* d, const uint32_t* a, const uint32_t* b) {
    asm volatile("mma.sync.aligned.m16n8k8.row.col.f32.tf32.tf32.f32 "
                 "{%0,%1,%2,%3}, {%4,%5,%6,%7}, {%8,%9}, {%0,%1,%2,%3};"
                 : "+f"(d[0]), "+f"(d[1]), "+f"(d[2]), "+f"(d[3])
                 : "r"(a[0]), "r"(a[1]), "r"(a[2]), "r"(a[3]), "r"(b[0]), "r"(b[1]));
}
#define CP_ASYNC16(dst, src, sz) \
    asm volatile("cp.async.cg.shared.global [%0], [%1], 16, %2;" :: "r"(dst), "l"(src), "r"(sz) : "memory")
#define CP_COMMIT() asm volatile("cp.async.commit_group;" ::: "memory")
#define CP_WAIT(n)  asm volatile("cp.async.wait_group %0;" :: "n"(n) : "memory")

// ---------------- kernel 0: x NCHW -> NHWC tf32 (channel-permuted) ----------------
__global__ void k_transpose_x(const float* __restrict__ x) {
    __shared__ float tile[32][33];
    int z = blockIdx.z;
    int n = z / Hh;
    int y = z % Hh;
    int xb = blockIdx.x * 32;
    int cb = blockIdx.y * 32;
    int tx = threadIdx.x, ty = threadIdx.y;
#pragma unroll
    for (int k = 0; k < 4; k++) {
        int c = cb + ty + k * 8;
        tile[ty + k * 8][tx] = x[((n * Cc + c) * Hh + y) * Ww + xb + tx];
    }
    __syncthreads();
    int c = cb + tx;
    int s = (c & 56) | ((c & 3) << 1) | ((c >> 2) & 1);   // permuted position
#pragma unroll
    for (int k = 0; k < 4; k++) {
        int xo = xb + ty + k * 8;
        g_xtf[((n * Hh + y) * Ww + xo) * Cc + s] = f2tf32(tile[tx][ty + k * 8]);
    }
}

// ---------------- kernel 0b: both weight arrays -> fragment-major (uint4/k-step) ----------------
__global__ void k_prep_w(const float* __restrict__ weight, const float* __restrict__ w_off) {
    int gidx = blockIdx.x * 256 + threadIdx.x;
    if (gidx < KK9 * 4096) {
        int idx = gidx;
        int j = idx & 1;
        int nt = (idx >> 1) & 1;
        int lane = (idx >> 2) & 31;
        int kk = (idx >> 7) & 7;
        int cog = (idx >> 10) & 3;
        int t = idx >> 12;
        int co = cog * 16 + nt * 8 + (lane >> 2);
        int c = kk * 8 + (lane & 3) + 4 * j;
        g_wtf[idx] = f2tf32(weight[(co * Cc + c) * KK9 + t]);
    } else if (gidx < KK9 * 4096 + KK9 * 2048) {
        int idx = gidx - KK9 * 4096;
        int j = idx & 1;
        int nt = (idx >> 1) & 1;
        int lane = (idx >> 2) & 31;
        int kk = (idx >> 7) & 7;
        int cog = (idx >> 10) & 1;
        int t = idx >> 11;
        int ch = cog * 16 + nt * 8 + (lane >> 2);
        int c = kk * 8 + (lane & 3) + 4 * j;
        g_wofff[idx] = (ch < 27) ? f2tf32(w_off[(ch * Cc + c) * KK9 + t]) : 0u;
    }
}

// ---------------- fused kernel: offconv (TC) -> metadata -> deform (TC) ----------------
#define A_STRIDE 72                            // 72 ≡ 8 (mod 32): conflict-free LDS.64 frags
#define O_STRIDE 132
#define BUFW (128 * A_STRIDE)                  // 9216 words per val buffer
#define SM_ENTW (2 * BUFW * 4)                 // 73728
#define SM_ENTB (SM_ENTW + 1152 * 16)          // 92160  (obase overlays here)
#define SM_ENTD (SM_ENTB + 1152 * 4)           // 96768
#define FUSED_SMEM (SM_ENTD + 1152 * 4)        // 101376

__global__ void __launch_bounds__(512, 2) k_fused(const float* __restrict__ b_off,
                                                  const float* __restrict__ bias,
                                                  float* __restrict__ out) {
    extern __shared__ char base[];
    uint32_t* valS = (uint32_t*)base;                // [2][128][72]
    float4*   entW = (float4*)(base + SM_ENTW);
    int*      entB = (int*)(base + SM_ENTB);
    int*      entD = (int*)(base + SM_ENTD);
    int*      obase = entB;                          // overlay (dead before entB written)
    float*    offmS = (float*)base;                  // [128][28] overlay (written after phase A)
    float*    outS = (float*)base;                   // epilogue overlay [64co][132]
    uint32_t  valS_sm = smem_u32(valS);
    const float* xtf = (const float*)g_xtf;

    int tid = threadIdx.x;
    int wid = tid >> 5;
    int lane = tid & 31;
    int pix0 = blockIdx.x * 128;
    int nb = pix0 / HW;
    int rem0 = pix0 % HW;
    int lg = lane >> 2;
    int lt = lane & 3;

    // ============ phase A: offset conv (128pix x 32ch, warp tile 16pix x 16ch) ============
    for (int e = tid; e < KK9 * 128; e += 512) {
        int t = e >> 7;
        int pl = e & 127;
        int rem = rem0 + pl;
        int yy = rem / Ww + t / 3 - 1;
        int xx = rem % Ww + t % 3 - 1;
        obase[e] = ((unsigned)yy < Hh && (unsigned)xx < Ww)
                 ? ((nb * Hh + yy) * Ww + xx) * Cc : -1;
    }
    __syncthreads();

    int wmA = (wid & 7) * 16;     // warp pixel base (phase A)
    int cogA = wid >> 3;          // ch group (16 ch)

    float accA[2][4];
#pragma unroll
    for (int nt = 0; nt < 2; nt++)
#pragma unroll
        for (int r = 0; r < 4; r++) accA[nt][r] = 0.f;

    auto fillA = [&](int tt, int b) {
        uint32_t dbase = valS_sm + b * (BUFW * 4);
#pragma unroll
        for (int j = 0; j < 4; j++) {
            int idx = tid + j * 512;
            int pl = idx >> 4;
            int c4 = (idx & 15) << 2;
            int gb = obase[tt * 128 + pl];
            const uint32_t* src = &g_xtf[(gb < 0 ? 0 : gb) + c4];
            CP_ASYNC16(dbase + (pl * A_STRIDE + c4) * 4, src, (gb < 0) ? 0 : 16);
        }
        CP_COMMIT();
    };

    fillA(0, 0);
    for (int t = 0; t < KK9; t++) {
        if (t < KK9 - 1) {
            fillA(t + 1, (t + 1) & 1);
            CP_WAIT(1);
        } else {
            CP_WAIT(0);
        }
        __syncthreads();
        const uint32_t* cur = valS + (t & 1) * BUFW;
#pragma unroll
        for (int kk = 0; kk < 8; kk++) {
            int k0 = kk * 8 + 2 * lt;
            uint2 p0 = *(const uint2*)&cur[(wmA + lg) * A_STRIDE + k0];
            uint2 p1 = *(const uint2*)&cur[(wmA + 8 + lg) * A_STRIDE + k0];
            uint32_t a[4] = {p0.x, p1.x, p0.y, p1.y};
            uint4 bv = ((const uint4*)&g_wofff[((t * 2 + cogA) * 8 + kk) * 128])[lane];
            uint32_t b0[2] = {bv.x, bv.y};
            uint32_t b1[2] = {bv.z, bv.w};
            mma_tf32(accA[0], a, b0);
            mma_tf32(accA[1], a, b1);
        }
        __syncthreads();
    }

    // phase A epilogue -> offmS (overlays buf0; loop is done)
#pragma unroll
    for (int nt = 0; nt < 2; nt++)
#pragma unroll
        for (int r = 0; r < 4; r++) {
            int pix = wmA + ((r >> 1) << 3) + lg;
            int ch = cogA * 16 + nt * 8 + 2 * lt + (r & 1);
            if (ch < 27) {
                float v = accA[nt][r] + __ldg(&b_off[ch]);
                if (ch >= 18) v = 1.f / (1.f + __expf(-v));
                offmS[pix * 28 + ch] = v;
            }
        }
    __syncthreads();

    // ============ metadata: bilinear coefficients for all 9 taps ============
    for (int e = tid; e < KK9 * 128; e += 512) {
        int t = e >> 7;
        int pl = e & 127;
        int rem = rem0 + pl;
        int y = rem / Ww;
        int x = rem % Ww;
        float dy = offmS[pl * 28 + 2 * t];
        float dx = offmS[pl * 28 + 2 * t + 1];
        float m = offmS[pl * 28 + 18 + t];
        int ky = t / 3, kx = t % 3;
        float py = (float)(y + ky - 1) + dy;
        float px = (float)(x + kx - 1) + dx;
        float fy = floorf(py), fx = floorf(px);
        float ly = py - fy, lx = px - fx;
        int iy = (int)fy, ix = (int)fx;
        float hy0 = (iy >= 0 && iy < Hh) ? (1.f - ly) : 0.f;
        float hy1 = (iy >= -1 && iy < Hh - 1) ? ly : 0.f;
        float hx0 = (ix >= 0 && ix < Ww) ? (1.f - lx) : 0.f;
        float hx1 = (ix >= -1 && ix < Ww - 1) ? lx : 0.f;
        int iyc = min(max(iy, 0), Hh - 1);
        int ixc = min(max(ix, 0), Ww - 1);
        int ddy = (iy >= 0 && iy < Hh - 1) ? Ww * Cc : 0;
        int ddx = (ix >= 0 && ix < Ww - 1) ? Cc : 0;
        entB[e] = ((nb * Hh + iyc) * Ww + ixc) * Cc;   // overwrites obase (dead)
        entD[e] = ddx | (ddy << 16);
        entW[e] = make_float4(hy0 * hx0 * m, hy0 * hx1 * m, hy1 * hx0 * m, hy1 * hx1 * m);
    }

    // ============ phase B: deform (128pix x 64co, warp tile 32pix x 16co) ============
    int wm = (wid & 3) * 32;
    int cog = wid >> 2;
    int c4 = (tid & 15) << 2;     // gather channel position (float4 granule)
    int q4 = tid >> 4;            // gather pixel phase (0..31)

    float acc[2][2][4];
#pragma unroll
    for (int mt = 0; mt < 2; mt++)
#pragma unroll
        for (int nt = 0; nt < 2; nt++)
#pragma unroll
            for (int r = 0; r < 4; r++) acc[mt][nt][r] = 0.f;
    __syncthreads();              // metadata visible; offmS/valS free

    // vectorized gather of tap -> buffer
    auto gatherB = [&](int tt, uint32_t* dst) {
        int tb = tt * 128;
#pragma unroll
        for (int s = 0; s < 4; s++) {
            int pl = s * 32 + q4;
            int e = tb + pl;
            float4 w = entW[e];
            int gbase = entB[e] + c4;
            int dd = entD[e];
            int ddx = dd & 0xffff;
            int ddy = dd >> 16;
            float4 v00 = *(const float4*)&xtf[gbase];
            float4 v01 = *(const float4*)&xtf[gbase + ddx];
            float4 v10 = *(const float4*)&xtf[gbase + ddy];
            float4 v11 = *(const float4*)&xtf[gbase + ddy + ddx];
            uint4 o;
            o.x = f2tf32(w.x * v00.x + w.y * v01.x + w.z * v10.x + w.w * v11.x);
            o.y = f2tf32(w.x * v00.y + w.y * v01.y + w.z * v10.y + w.w * v11.y);
            o.z = f2tf32(w.x * v00.z + w.y * v01.z + w.z * v10.z + w.w * v11.z);
            o.w = f2tf32(w.x * v00.w + w.y * v01.w + w.z * v10.w + w.w * v11.w);
            *(uint4*)&dst[pl * A_STRIDE + c4] = o;
        }
    };

    // prologue gather: tap 0 -> buf 0
    gatherB(0, valS);
    __syncthreads();

    for (int t = 0; t < KK9; t++) {
        const uint32_t* cur = valS + (t & 1) * BUFW;
#pragma unroll
        for (int kk = 0; kk < 8; kk++) {
            int k0 = kk * 8 + 2 * lt;
            uint32_t a[2][4];
#pragma unroll
            for (int mt = 0; mt < 2; mt++) {
                uint2 p0 = *(const uint2*)&cur[(wm + mt * 16 + lg) * A_STRIDE + k0];
                uint2 p1 = *(const uint2*)&cur[(wm + mt * 16 + 8 + lg) * A_STRIDE + k0];
                a[mt][0] = p0.x; a[mt][1] = p1.x; a[mt][2] = p0.y; a[mt][3] = p1.y;
            }
            uint4 bv = ((const uint4*)&g_wtf[((t * 4 + cog) * 8 + kk) * 128])[lane];
            uint32_t b0[2] = {bv.x, bv.y};
            uint32_t b1[2] = {bv.z, bv.w};
#pragma unroll
            for (int mt = 0; mt < 2; mt++) {
                mma_tf32(acc[mt][0], a[mt], b0);
                mma_tf32(acc[mt][1], a[mt], b1);
            }
        }
        if (t < KK9 - 1) {
            gatherB(t + 1, valS + ((t + 1) & 1) * BUFW);
        }
        __syncthreads();
    }

    // epilogue: fragments -> smem [co][pix] -> coalesced NCHW stores
#pragma unroll
    for (int mt = 0; mt < 2; mt++)
#pragma unroll
        for (int nt = 0; nt < 2; nt++)
#pragma unroll
            for (int r = 0; r < 4; r++) {
                int pix = wm + mt * 16 + ((r >> 1) << 3) + lg;
                int co = cog * 16 + nt * 8 + 2 * lt + (r & 1);
                outS[co * O_STRIDE + pix] = acc[mt][nt][r];
            }
    __syncthreads();

#pragma unroll
    for (int i = 0; i < 4; i++) {
        int co = i * 16 + wid;
        int px = lane * 4;
        float4 v = *(const float4*)&outS[co * O_STRIDE + px];
        float bv = __ldg(&bias[co]);
        v.x += bv; v.y += bv; v.z += bv; v.w += bv;
        *(float4*)&out[((size_t)nb * COo + co) * HW + rem0 + px] = v;
    }
}

// ---------------- launch ----------------
extern "C" void kernel_launch(void* const* d_in, const int* in_sizes, int n_in,
                              void* d_out, int out_size) {
    const float* x      = (const float*)d_in[0];
    const float* w_off  = (const float*)d_in[1];
    const float* b_off  = (const float*)d_in[2];
    const float* weight = (const float*)d_in[3];
    const float* bias   = (const float*)d_in[4];
    float* out = (float*)d_out;

    static int attr_set = 0;
    if (!attr_set) {
        cudaFuncSetAttribute(k_fused, cudaFuncAttributeMaxDynamicSharedMemorySize, FUSED_SMEM);
        attr_set = 1;
    }

    k_transpose_x<<<dim3(3, 2, Nn * Hh), dim3(32, 8)>>>(x);
    k_prep_w<<<(KK9 * 4096 + KK9 * 2048 + 255) / 256, 256>>>(weight, w_off);
    k_fused<<<NPIX / 128, 512, FUSED_SMEM>>>(b_off, bias, out);
}